// round 10
// baseline (speedup 1.0000x reference)
#include <cuda_runtime.h>
#include <math.h>
#include <stdint.h>

constexpr size_t FS = (size_t)16384 * 512;

__device__ float g_f[3 * FS];                       // projected features (tf32-rounded)
__device__ float g_att[FS];                         // attention out (tf32-rounded)
__device__ float g_win[512 * 512];
__device__ float g_wout[512 * 512];
__device__ float g_norms[2 * 512 * 256];            // qn,kn [t][hb][n]
__device__ float g_part[2048];                      // stats partials [t][c][s][2]
__device__ float g_mu[49152];
__device__ float g_rs[49152];

__device__ __forceinline__ float warp_sum(float v) {
    #pragma unroll
    for (int o = 16; o; o >>= 1) v += __shfl_xor_sync(0xffffffffu, v, o);
    return v;
}
__device__ __forceinline__ float tf32r(float x) {
    uint32_t u;
    asm("cvt.rna.tf32.f32 %0, %1;" : "=r"(u) : "f"(x));
    return __uint_as_float(u);
}
__device__ __forceinline__ void mma8(float c[4], const uint32_t a[4], uint32_t b0, uint32_t b1) {
    asm volatile(
        "mma.sync.aligned.m16n8k8.row.col.f32.tf32.tf32.f32 "
        "{%0,%1,%2,%3},{%4,%5,%6,%7},{%8,%9},{%0,%1,%2,%3};"
        : "+f"(c[0]), "+f"(c[1]), "+f"(c[2]), "+f"(c[3])
        : "r"(a[0]), "r"(a[1]), "r"(a[2]), "r"(a[3]), "r"(b0), "r"(b1));
}

// ---------------- 0) round weights once ----------------
__global__ __launch_bounds__(256) void wround_kernel(
    const float* __restrict__ Win, const float* __restrict__ Wout)
{
    int idx = (blockIdx.x * 256 + threadIdx.x) * 4;
    float4 a = *(const float4*)(Win + idx);
    a.x = tf32r(a.x); a.y = tf32r(a.y); a.z = tf32r(a.z); a.w = tf32r(a.w);
    *(float4*)(g_win + idx) = a;
    float4 b = *(const float4*)(Wout + idx);
    b.x = tf32r(b.x); b.y = tf32r(b.y); b.z = tf32r(b.z); b.w = tf32r(b.w);
    *(float4*)(g_wout + idx) = b;
}

// ---------------- 1) LN row statistics (no big write) ----------------
__global__ __launch_bounds__(256) void ln_stats_kernel(
    const float* __restrict__ q, const float* __restrict__ k, const float* __restrict__ v)
{
    int warp = threadIdx.x >> 5, lane = threadIdx.x & 31;
    int row = blockIdx.x * 8 + warp;
    int t = row >> 14, r = row & 16383;
    const float* src = (t == 0 ? q : (t == 1 ? k : v)) + (size_t)r * 512;
    float x[16], s = 0.f;
    #pragma unroll
    for (int i = 0; i < 16; i++) { x[i] = src[lane + 32 * i]; s += x[i]; }
    s = warp_sum(s);
    float mu = s * (1.f / 512.f), ss = 0.f;
    #pragma unroll
    for (int i = 0; i < 16; i++) { float d = x[i] - mu; ss += d * d; }
    ss = warp_sum(ss);
    if (!lane) { g_mu[row] = mu; g_rs[row] = rsqrtf(ss * (1.f / 512.f) + 1e-5f); }
}

// ---------------- 2/6) tf32 GEMM 128x128, BK=16, LN fused in A prefetch ----------------
template<bool PROJ>
__global__ __launch_bounds__(256) void mm_kernel(
    const float* __restrict__ A,
    const float* __restrict__ q, const float* __restrict__ kk_, const float* __restrict__ vv_,
    const float* __restrict__ gma, const float* __restrict__ bta,
    const float* __restrict__ B, float* __restrict__ C, const float* __restrict__ bias,
    int rowoff)
{
    __shared__ float As[2][128 * 20];
    __shared__ float Bs[2][16 * 136];

    int tid = threadIdx.x, lane = tid & 31, wid = tid >> 5;
    int g = lane >> 2, t4 = lane & 3;
    int wm = (wid >> 1) * 32, wn = (wid & 1) * 64;
    int bx = blockIdx.x;
    int grow = (blockIdx.y + rowoff) * 128;

    int arow = tid >> 2, ac4 = (tid & 3) * 4;
    const float* srcA[2];
    float mu[2], rs[2];
    if (PROJ) {
        int t = grow >> 14;
        int r0 = grow & 16383;
        const float* base = (t == 0 ? q : (t == 1 ? kk_ : vv_));
        #pragma unroll
        for (int l = 0; l < 2; l++) {
            srcA[l] = base + (size_t)(r0 + l * 64 + arow) * 512;
            mu[l] = g_mu[grow + l * 64 + arow];
            rs[l] = g_rs[grow + l * 64 + arow];
        }
    } else {
        #pragma unroll
        for (int l = 0; l < 2; l++)
            srcA[l] = A + (size_t)(grow + l * 64 + arow) * 512;
    }
    const float* Bbase = B + (size_t)bx * 128 + lane * 4;

    float acc[2][8][4] = {};
    float4 pA[2], pB[2];

    #pragma unroll
    for (int l = 0; l < 2; l++) {
        float4 x = *(const float4*)(srcA[l] + ac4);
        if (PROJ) {
            float4 g4 = *(const float4*)(gma + ac4);
            float4 b4 = *(const float4*)(bta + ac4);
            x.x = tf32r((x.x - mu[l]) * rs[l] * g4.x + b4.x);
            x.y = tf32r((x.y - mu[l]) * rs[l] * g4.y + b4.y);
            x.z = tf32r((x.z - mu[l]) * rs[l] * g4.z + b4.z);
            x.w = tf32r((x.w - mu[l]) * rs[l] * g4.w + b4.w);
        }
        *(float4*)&As[0][(l * 64 + arow) * 20 + ac4] = x;
        *(float4*)&Bs[0][(l * 8 + wid) * 136 + lane * 4] =
            *(const float4*)(Bbase + (size_t)(l * 8 + wid) * 512);
    }
    __syncthreads();

    int buf = 0;
    for (int bk = 0; bk < 512; bk += 16) {
        bool more = (bk + 16) < 512;
        if (more) {
            #pragma unroll
            for (int l = 0; l < 2; l++) {
                float4 x = *(const float4*)(srcA[l] + bk + 16 + ac4);
                if (PROJ) {
                    float4 g4 = *(const float4*)(gma + bk + 16 + ac4);
                    float4 b4 = *(const float4*)(bta + bk + 16 + ac4);
                    x.x = tf32r((x.x - mu[l]) * rs[l] * g4.x + b4.x);
                    x.y = tf32r((x.y - mu[l]) * rs[l] * g4.y + b4.y);
                    x.z = tf32r((x.z - mu[l]) * rs[l] * g4.z + b4.z);
                    x.w = tf32r((x.w - mu[l]) * rs[l] * g4.w + b4.w);
                }
                pA[l] = x;
                pB[l] = *(const float4*)(Bbase + (size_t)(bk + 16 + l * 8 + wid) * 512);
            }
        }
        #pragma unroll
        for (int ks = 0; ks < 2; ks++) {
            int kb = ks * 8;
            uint32_t af[2][4];
            #pragma unroll
            for (int mi = 0; mi < 2; mi++) {
                const float* ap = &As[buf][(wm + mi * 16) * 20 + kb];
                af[mi][0] = __float_as_uint(ap[g * 20 + t4]);
                af[mi][1] = __float_as_uint(ap[(g + 8) * 20 + t4]);
                af[mi][2] = __float_as_uint(ap[g * 20 + t4 + 4]);
                af[mi][3] = __float_as_uint(ap[(g + 8) * 20 + t4 + 4]);
            }
            #pragma unroll
            for (int ni = 0; ni < 8; ni++) {
                uint32_t b0 = __float_as_uint(Bs[buf][(kb + t4) * 136 + wn + ni * 8 + g]);
                uint32_t b1 = __float_as_uint(Bs[buf][(kb + t4 + 4) * 136 + wn + ni * 8 + g]);
                mma8(acc[0][ni], af[0], b0, b1);
                mma8(acc[1][ni], af[1], b0, b1);
            }
        }
        if (more) {
            #pragma unroll
            for (int l = 0; l < 2; l++) {
                *(float4*)&As[buf ^ 1][(l * 64 + arow) * 20 + ac4] = pA[l];
                *(float4*)&Bs[buf ^ 1][(l * 8 + wid) * 136 + lane * 4] = pB[l];
            }
            __syncthreads();
            buf ^= 1;
        }
    }

    if (PROJ) {
        #pragma unroll
        for (int mi = 0; mi < 2; mi++)
            #pragma unroll
            for (int ni = 0; ni < 8; ni++)
                #pragma unroll
                for (int p = 0; p < 4; p++)
                    acc[mi][ni][p] = tf32r(acc[mi][ni][p]);
    }

    #pragma unroll
    for (int mi = 0; mi < 2; mi++) {
        #pragma unroll
        for (int ni = 0; ni < 8; ni++) {
            int col = bx * 128 + wn + ni * 8 + 2 * t4;
            float2 o0 = make_float2(acc[mi][ni][0], acc[mi][ni][1]);
            float2 o1 = make_float2(acc[mi][ni][2], acc[mi][ni][3]);
            if (!PROJ) {
                float2 bb = *(const float2*)(bias + col);
                o0.x += bb.x; o0.y += bb.y; o1.x += bb.x; o1.y += bb.y;
            }
            int r0 = grow + wm + mi * 16 + g;
            *(float2*)(C + (size_t)r0 * 512 + col) = o0;
            *(float2*)(C + (size_t)(r0 + 8) * 512 + col) = o1;
        }
    }

    if (PROJ && (grow >> 14) < 2) {
        int t = grow >> 14;
        int h = bx * 2 + (wid & 1);
        #pragma unroll
        for (int mi = 0; mi < 2; mi++) {
            #pragma unroll
            for (int half = 0; half < 2; half++) {
                float s = 0.f;
                #pragma unroll
                for (int ni = 0; ni < 8; ni++) {
                    float x = acc[mi][ni][2 * half], y = acc[mi][ni][2 * half + 1];
                    s += x * x + y * y;
                }
                s += __shfl_xor_sync(0xffffffffu, s, 1);
                s += __shfl_xor_sync(0xffffffffu, s, 2);
                if (t4 == 0) {
                    int gr = grow + wm + mi * 16 + g + 8 * half;
                    int r = gr & 16383, bb = r >> 8, n = r & 255;
                    g_norms[t * 131072 + (h * 64 + bb) * 256 + n] = sqrtf(s);
                }
            }
        }
    }
}

// ---------------- 3) chunk stats: raw Gram (tf32 mma) + rank-1 correction ----------------
__global__ __launch_bounds__(256) void stats_kernel()
{
    extern __shared__ float sE[];        // [256][72]
    __shared__ float red[256];
    __shared__ float smu[64];
    __shared__ float r3[3][8];

    int tid = threadIdx.x;
    int bx = blockIdx.x;
    int t = bx >> 9;
    int rest = bx & 511;
    int c = rest >> 3, s = rest & 7;
    int h = c >> 3, b = ((c & 7) << 3) + s;
    const float* base = g_f + (size_t)t * FS + (size_t)(b * 256) * 512 + h * 64;

    for (int idx = tid; idx < 4096; idx += 256) {
        int n = idx >> 4, c4 = (idx & 15) * 4;
        *(float4*)&sE[n * 72 + c4] = *(const float4*)(base + (size_t)n * 512 + c4);
    }
    __syncthreads();

    {
        int i = tid & 63, grp = tid >> 6;
        float sm = 0.f;
        #pragma unroll 8
        for (int n = grp; n < 256; n += 4) sm += sE[n * 72 + i];
        red[tid] = sm;
        __syncthreads();
        if (tid < 64)
            smu[tid] = (red[tid] + red[tid + 64] + red[tid + 128] + red[tid + 192]) * (1.f / 256.f);
        __syncthreads();
    }

    int lane = tid & 31, wid = tid >> 5;
    int g = lane >> 2, t4 = lane & 3;
    int wm = (wid & 3) * 16, wn = (wid >> 2) * 32;
    float gacc[4][4] = {};
    #pragma unroll 4
    for (int ks = 0; ks < 32; ks++) {
        int kb8 = ks * 8;
        uint32_t af[4];
        af[0] = __float_as_uint(sE[(kb8 + t4) * 72 + wm + g]);
        af[1] = __float_as_uint(sE[(kb8 + t4) * 72 + wm + g + 8]);
        af[2] = __float_as_uint(sE[(kb8 + t4 + 4) * 72 + wm + g]);
        af[3] = __float_as_uint(sE[(kb8 + t4 + 4) * 72 + wm + g + 8]);
        #pragma unroll
        for (int ni = 0; ni < 4; ni++) {
            uint32_t b0 = __float_as_uint(sE[(kb8 + t4) * 72 + wn + ni * 8 + g]);
            uint32_t b1 = __float_as_uint(sE[(kb8 + t4 + 4) * 72 + wn + ni * 8 + g]);
            mma8(gacc[ni], af, b0, b1);
        }
    }

    int row0 = wm + g, row1 = wm + g + 8;
    float mr0 = smu[row0] * 256.f, mr1 = smu[row1] * 256.f;
    float tot = 0.f, dsum = 0.f, vsum = 0.f;
    #pragma unroll
    for (int ni = 0; ni < 4; ni++) {
        int c0 = wn + ni * 8 + 2 * t4, c1 = c0 + 1;
        float mc0 = smu[c0], mc1 = smu[c1];
        float g00 = gacc[ni][0] - mr0 * mc0;
        float g01 = gacc[ni][1] - mr0 * mc1;
        float g10 = gacc[ni][2] - mr1 * mc0;
        float g11 = gacc[ni][3] - mr1 * mc1;
        tot += g00 * g00 + g01 * g01 + g10 * g10 + g11 * g11;
        if (row0 == c0) { dsum += g00 * g00; vsum += fmaxf(0.f, 1.f - sqrtf(g00 * (1.f / 255.f) + 1e-8f)); }
        if (row0 == c1) { dsum += g01 * g01; vsum += fmaxf(0.f, 1.f - sqrtf(g01 * (1.f / 255.f) + 1e-8f)); }
        if (row1 == c0) { dsum += g10 * g10; vsum += fmaxf(0.f, 1.f - sqrtf(g10 * (1.f / 255.f) + 1e-8f)); }
        if (row1 == c1) { dsum += g11 * g11; vsum += fmaxf(0.f, 1.f - sqrtf(g11 * (1.f / 255.f) + 1e-8f)); }
    }

    float a0 = warp_sum(tot), a1 = warp_sum(dsum), a2 = warp_sum(vsum);
    if (!lane) { r3[0][wid] = a0; r3[1][wid] = a1; r3[2][wid] = a2; }
    __syncthreads();
    if (tid == 0) {
        float T = 0.f, D = 0.f, V = 0.f;
        #pragma unroll
        for (int i = 0; i < 8; i++) { T += r3[0][i]; D += r3[1][i]; V += r3[2][i]; }
        g_part[bx * 2 + 0] = V * (1.f / 512.f);
        g_part[bx * 2 + 1] = (T - D) * (1.f / (255.f * 255.f * 64.f * 8.f));
    }
}

// ---------------- 4) fused attention (batch-major y for splitting) ----------------
__global__ __launch_bounds__(256) void attn_kernel(
    const float* __restrict__ cl, const float* __restrict__ vl, int yoff)
{
    extern __shared__ float sh[];
    float* Qs  = sh;                       // [128][68]
    float* Ks  = sh + 128 * 68;            // [64][68]
    float* Vs  = sh + 128 * 68 + 64 * 68;  // [64][72]
    float* Ssm = Vs + 64 * 72;             // [128][68]

    int tid = threadIdx.x, lane = tid & 31, wid = tid >> 5;
    int g = lane >> 2, t4 = lane & 3;
    int wm = (wid >> 1) * 32, wn = (wid & 1) * 32;
    int nt = blockIdx.x;
    int y = blockIdx.y + yoff;             // b*8 + h
    int h = y & 7, b = y >> 3;
    int hb = h * 64 + b;
    int c = h * 8 + (b >> 3);

    const float* qb = g_f + (size_t)(b * 256 + nt * 128) * 512 + h * 64;
    const float* kb = g_f + FS + (size_t)(b * 256) * 512 + h * 64;
    const float* vb = g_f + 2 * FS + (size_t)(b * 256) * 512 + h * 64;

    {
        int lrow = tid >> 4, lc4 = (tid & 15) * 4;
        #pragma unroll
        for (int l = 0; l < 8; l++) {
            int row = l * 16 + lrow;
            *(float4*)&Qs[row * 68 + lc4] = *(const float4*)(qb + (size_t)row * 512 + lc4);
        }
    }

    float cw = 1.f / (1.f + expf(-cl[0]));
    float vw = 1.f / (1.f + expf(-vl[0]));
    float cosw = 1.f - cw - vw;
    float Vq = 0.f, Cq = 0.f, Vk = 0.f, Ck = 0.f;
    #pragma unroll
    for (int s = 0; s < 8; s++) {
        Vq += g_part[(c * 8 + s) * 2];
        Cq += g_part[(c * 8 + s) * 2 + 1];
        Vk += g_part[(512 + c * 8 + s) * 2];
        Ck += g_part[(512 + c * 8 + s) * 2 + 1];
    }
    float biasv = cw * (Cq * Ck) + vw * (Vq * Vk);

    float qinv[2][2];
    #pragma unroll
    for (int mi = 0; mi < 2; mi++)
        #pragma unroll
        for (int half = 0; half < 2; half++) {
            int n = nt * 128 + wm + mi * 16 + g + 8 * half;
            qinv[mi][half] = cosw / g_norms[hb * 256 + n];
        }

    int krow = tid >> 2;
    int kc0 = (tid & 3) * 4;

    float oacc[2][4][4] = {};
    for (int mc = 0; mc < 4; mc++) {
        #pragma unroll
        for (int l = 0; l < 4; l++) {
            int col = kc0 + l * 16;
            *(float4*)&Ks[krow * 68 + col] =
                *(const float4*)(kb + (size_t)(mc * 64 + krow) * 512 + col);
            *(float4*)&Vs[krow * 72 + col] =
                *(const float4*)(vb + (size_t)(mc * 64 + krow) * 512 + col);
        }
        __syncthreads();

        float sacc[2][4][4] = {};
        #pragma unroll
        for (int ks = 0; ks < 8; ks++) {
            int kb8 = ks * 8;
            uint32_t af[2][4];
            #pragma unroll
            for (int mi = 0; mi < 2; mi++) {
                const float* ap = &Qs[(wm + mi * 16) * 68 + kb8];
                af[mi][0] = __float_as_uint(ap[g * 68 + t4]);
                af[mi][1] = __float_as_uint(ap[(g + 8) * 68 + t4]);
                af[mi][2] = __float_as_uint(ap[g * 68 + t4 + 4]);
                af[mi][3] = __float_as_uint(ap[(g + 8) * 68 + t4 + 4]);
            }
            #pragma unroll
            for (int ni = 0; ni < 4; ni++) {
                uint32_t b0 = __float_as_uint(Ks[(wn + ni * 8 + g) * 68 + kb8 + t4]);
                uint32_t b1 = __float_as_uint(Ks[(wn + ni * 8 + g) * 68 + kb8 + t4 + 4]);
                mma8(sacc[0][ni], af[0], b0, b1);
                mma8(sacc[1][ni], af[1], b0, b1);
            }
        }

        #pragma unroll
        for (int ni = 0; ni < 4; ni++) {
            int ml = wn + ni * 8 + 2 * t4;
            int m0 = mc * 64 + ml;
            float ki0 = 1.f / g_norms[131072 + hb * 256 + m0];
            float ki1 = 1.f / g_norms[131072 + hb * 256 + m0 + 1];
            #pragma unroll
            for (int mi = 0; mi < 2; mi++) {
                #pragma unroll
                for (int half = 0; half < 2; half++) {
                    int nl = wm + mi * 16 + g + 8 * half;
                    float2 o = make_float2(
                        tf32r(qinv[mi][half] * sacc[mi][ni][2 * half] * ki0 + biasv),
                        tf32r(qinv[mi][half] * sacc[mi][ni][2 * half + 1] * ki1 + biasv));
                    *(float2*)&Ssm[nl * 68 + ml] = o;
                }
            }
        }
        __syncthreads();

        #pragma unroll
        for (int ks = 0; ks < 8; ks++) {
            int kb8 = ks * 8;
            uint32_t af[2][4];
            #pragma unroll
            for (int mi = 0; mi < 2; mi++) {
                const float* ap = &Ssm[(wm + mi * 16) * 68 + kb8];
                af[mi][0] = __float_as_uint(ap[g * 68 + t4]);
                af[mi][1] = __float_as_uint(ap[(g + 8) * 68 + t4]);
                af[mi][2] = __float_as_uint(ap[g * 68 + t4 + 4]);
                af[mi][3] = __float_as_uint(ap[(g + 8) * 68 + t4 + 4]);
            }
            #pragma unroll
            for (int ni = 0; ni < 4; ni++) {
                uint32_t b0 = __float_as_uint(Vs[(kb8 + t4) * 72 + wn + ni * 8 + g]);
                uint32_t b1 = __float_as_uint(Vs[(kb8 + t4 + 4) * 72 + wn + ni * 8 + g]);
                mma8(oacc[0][ni], af[0], b0, b1);
                mma8(oacc[1][ni], af[1], b0, b1);
            }
        }
        __syncthreads();
    }

    #pragma unroll
    for (int mi = 0; mi < 2; mi++) {
        #pragma unroll
        for (int ni = 0; ni < 4; ni++) {
            int col = wn + ni * 8 + 2 * t4;
            int n0 = nt * 128 + wm + mi * 16 + g;
            *(float2*)(g_att + (size_t)(b * 256 + n0) * 512 + h * 64 + col) =
                make_float2(tf32r(oacc[mi][ni][0]), tf32r(oacc[mi][ni][1]));
            *(float2*)(g_att + (size_t)(b * 256 + n0 + 8) * 512 + h * 64 + col) =
                make_float2(tf32r(oacc[mi][ni][2]), tf32r(oacc[mi][ni][3]));
        }
    }
}

// ---------------- launch ----------------
extern "C" void kernel_launch(void* const* d_in, const int* in_sizes, int n_in,
                              void* d_out, int out_size)
{
    const float* q   = (const float*)d_in[0];
    const float* k   = (const float*)d_in[1];
    const float* v   = (const float*)d_in[2];
    const float* gma = (const float*)d_in[3];
    const float* bta = (const float*)d_in[4];
    const float* Win = (const float*)d_in[5];
    const float* Wout= (const float*)d_in[6];
    const float* bout= (const float*)d_in[7];
    const float* covl= (const float*)d_in[8];
    const float* varl= (const float*)d_in[9];
    float* out = (float*)d_out;

    void *pf, *patt, *pwin, *pwout;
    cudaGetSymbolAddress(&pf, g_f);
    cudaGetSymbolAddress(&patt, g_att);
    cudaGetSymbolAddress(&pwin, g_win);
    cudaGetSymbolAddress(&pwout, g_wout);

    constexpr int ATTN_SMEM  = (128 * 68 + 64 * 68 + 64 * 72 + 128 * 68) * 4;
    constexpr int STATS_SMEM = 256 * 72 * 4;

    static cudaStream_t s2;
    static cudaEvent_t evRoot, evW, evQK, evS, evA1, evO1;
    static bool init_done = false;
    if (!init_done) {
        cudaFuncSetAttribute(attn_kernel,  cudaFuncAttributeMaxDynamicSharedMemorySize, ATTN_SMEM);
        cudaFuncSetAttribute(stats_kernel, cudaFuncAttributeMaxDynamicSharedMemorySize, STATS_SMEM);
        cudaStreamCreateWithFlags(&s2, cudaStreamNonBlocking);
        cudaEventCreateWithFlags(&evRoot, cudaEventDisableTiming);
        cudaEventCreateWithFlags(&evW, cudaEventDisableTiming);
        cudaEventCreateWithFlags(&evQK, cudaEventDisableTiming);
        cudaEventCreateWithFlags(&evS, cudaEventDisableTiming);
        cudaEventCreateWithFlags(&evA1, cudaEventDisableTiming);
        cudaEventCreateWithFlags(&evO1, cudaEventDisableTiming);
        init_done = true;
    }

    // fork s2 from the capturing stream
    cudaEventRecord(evRoot, 0);
    cudaStreamWaitEvent(s2, evRoot, 0);

    // wround on s2 concurrent with ln_stats on main
    wround_kernel<<<256, 256, 0, s2>>>(Win, Wout);
    cudaEventRecord(evW, s2);

    ln_stats_kernel<<<6144, 256>>>(q, k, v);
    cudaStreamWaitEvent(0, evW, 0);

    // proj q,k rows (LN fused)
    mm_kernel<true><<<dim3(4, 256), 256>>>(nullptr, q, k, v, gma, bta,
                                           (const float*)pwin, (float*)pf, nullptr, 0);
    cudaEventRecord(evQK, 0);

    // stats on s2, concurrent with proj_v
    cudaStreamWaitEvent(s2, evQK, 0);
    stats_kernel<<<1024, 256, STATS_SMEM, s2>>>();
    cudaEventRecord(evS, s2);

    // proj v rows (LN fused) on main
    mm_kernel<true><<<dim3(4, 128), 256>>>(nullptr, q, k, v, gma, bta,
                                           (const float*)pwin, (float*)pf, nullptr, 256);

    // join stats, then attention first half (b 0..31)
    cudaStreamWaitEvent(0, evS, 0);
    attn_kernel<<<dim3(2, 256), 256, ATTN_SMEM>>>(covl, varl, 0);
    cudaEventRecord(evA1, 0);

    // out-GEMM rows 0..8191 on s2, concurrent with attn second half
    cudaStreamWaitEvent(s2, evA1, 0);
    mm_kernel<false><<<dim3(4, 64), 256, 0, s2>>>((const float*)patt, nullptr, nullptr, nullptr,
                                                  nullptr, nullptr,
                                                  (const float*)pwout, out, bout, 0);
    cudaEventRecord(evO1, s2);

    // attention second half (b 32..63) on main
    attn_kernel<<<dim3(2, 256), 256, ATTN_SMEM>>>(covl, varl, 256);

    // out-GEMM rows 8192..16383 on main
    mm_kernel<false><<<dim3(4, 64), 256>>>((const float*)patt, nullptr, nullptr, nullptr,
                                           nullptr, nullptr,
                                           (const float*)pwout, out, bout, 64);

    // join s2 back before capture ends
    cudaStreamWaitEvent(0, evO1, 0);
}

// round 11
// speedup vs baseline: 1.0580x; 1.0580x over previous
#include <cuda_runtime.h>
#include <math.h>
#include <stdint.h>

constexpr size_t FS = (size_t)16384 * 512;

__device__ float g_xn[3 * FS];                      // LN output (tf32-rounded)
__device__ float g_f[3 * FS];                       // projected features (tf32-rounded)
__device__ float g_att[FS];                         // attention out (tf32-rounded)
__device__ float g_win[512 * 512];
__device__ float g_wout[512 * 512];
__device__ float g_norms[2 * 512 * 256];            // qn,kn [t][hb][n]
__device__ float g_part[2048];                      // stats partials [t][c][s][2]

__device__ __forceinline__ float warp_sum(float v) {
    #pragma unroll
    for (int o = 16; o; o >>= 1) v += __shfl_xor_sync(0xffffffffu, v, o);
    return v;
}
__device__ __forceinline__ float tf32r(float x) {
    uint32_t u;
    asm("cvt.rna.tf32.f32 %0, %1;" : "=r"(u) : "f"(x));
    return __uint_as_float(u);
}
__device__ __forceinline__ void mma8(float c[4], const uint32_t a[4], uint32_t b0, uint32_t b1) {
    asm volatile(
        "mma.sync.aligned.m16n8k8.row.col.f32.tf32.tf32.f32 "
        "{%0,%1,%2,%3},{%4,%5,%6,%7},{%8,%9},{%0,%1,%2,%3};"
        : "+f"(c[0]), "+f"(c[1]), "+f"(c[2]), "+f"(c[3])
        : "r"(a[0]), "r"(a[1]), "r"(a[2]), "r"(a[3]), "r"(b0), "r"(b1));
}

// ---------------- 0) round weights once ----------------
__global__ __launch_bounds__(256) void wround_kernel(
    const float* __restrict__ Win, const float* __restrict__ Wout)
{
    int idx = (blockIdx.x * 256 + threadIdx.x) * 4;
    float4 a = *(const float4*)(Win + idx);
    a.x = tf32r(a.x); a.y = tf32r(a.y); a.z = tf32r(a.z); a.w = tf32r(a.w);
    *(float4*)(g_win + idx) = a;
    float4 b = *(const float4*)(Wout + idx);
    b.x = tf32r(b.x); b.y = tf32r(b.y); b.z = tf32r(b.z); b.w = tf32r(b.w);
    *(float4*)(g_wout + idx) = b;
}

// ---------------- 1) LayerNorm, writes tf32-rounded output ----------------
__global__ __launch_bounds__(256) void ln_kernel(
    const float* __restrict__ q, const float* __restrict__ k, const float* __restrict__ v,
    const float* __restrict__ gma, const float* __restrict__ bta)
{
    int warp = threadIdx.x >> 5, lane = threadIdx.x & 31;
    int row = blockIdx.x * 8 + warp;
    int t = row >> 14, r = row & 16383;
    const float* src = (t == 0 ? q : (t == 1 ? k : v)) + (size_t)r * 512;
    float x[16], s = 0.f;
    #pragma unroll
    for (int i = 0; i < 16; i++) { x[i] = src[lane + 32 * i]; s += x[i]; }
    s = warp_sum(s);
    float mu = s * (1.f / 512.f), ss = 0.f;
    #pragma unroll
    for (int i = 0; i < 16; i++) { float d = x[i] - mu; ss += d * d; }
    ss = warp_sum(ss);
    float rs = rsqrtf(ss * (1.f / 512.f) + 1e-5f);
    float* dst = g_xn + (size_t)row * 512;
    #pragma unroll
    for (int i = 0; i < 16; i++) {
        int c = lane + 32 * i;
        dst[c] = tf32r((x[i] - mu) * rs * gma[c] + bta[c]);
    }
}

// ---------------- 2/6) tf32 GEMM 128x128, BK=16 (known good) + rowoff ----------------
template<bool PROJ>
__global__ __launch_bounds__(256) void mm_kernel(
    const float* __restrict__ A, const float* __restrict__ B,
    float* __restrict__ C, const float* __restrict__ bias, int rowoff)
{
    __shared__ float As[2][128 * 20];
    __shared__ float Bs[2][16 * 136];

    int tid = threadIdx.x, lane = tid & 31, wid = tid >> 5;
    int g = lane >> 2, t4 = lane & 3;
    int wm = (wid >> 1) * 32, wn = (wid & 1) * 64;
    int bx = blockIdx.x;
    int grow = (blockIdx.y + rowoff) * 128;

    int arow = tid >> 2, ac4 = (tid & 3) * 4;
    const float* srcA[2];
    #pragma unroll
    for (int l = 0; l < 2; l++)
        srcA[l] = A + (size_t)(grow + l * 64 + arow) * 512;
    const float* Bbase = B + (size_t)bx * 128 + lane * 4;

    float acc[2][8][4] = {};
    float4 pA[2], pB[2];

    #pragma unroll
    for (int l = 0; l < 2; l++) {
        *(float4*)&As[0][(l * 64 + arow) * 20 + ac4] = *(const float4*)(srcA[l] + ac4);
        *(float4*)&Bs[0][(l * 8 + wid) * 136 + lane * 4] =
            *(const float4*)(Bbase + (size_t)(l * 8 + wid) * 512);
    }
    __syncthreads();

    int buf = 0;
    for (int bk = 0; bk < 512; bk += 16) {
        bool more = (bk + 16) < 512;
        if (more) {
            #pragma unroll
            for (int l = 0; l < 2; l++) {
                pA[l] = *(const float4*)(srcA[l] + bk + 16 + ac4);
                pB[l] = *(const float4*)(Bbase + (size_t)(bk + 16 + l * 8 + wid) * 512);
            }
        }
        #pragma unroll
        for (int ks = 0; ks < 2; ks++) {
            int kb = ks * 8;
            uint32_t af[2][4];
            #pragma unroll
            for (int mi = 0; mi < 2; mi++) {
                const float* ap = &As[buf][(wm + mi * 16) * 20 + kb];
                af[mi][0] = __float_as_uint(ap[g * 20 + t4]);
                af[mi][1] = __float_as_uint(ap[(g + 8) * 20 + t4]);
                af[mi][2] = __float_as_uint(ap[g * 20 + t4 + 4]);
                af[mi][3] = __float_as_uint(ap[(g + 8) * 20 + t4 + 4]);
            }
            #pragma unroll
            for (int ni = 0; ni < 8; ni++) {
                uint32_t b0 = __float_as_uint(Bs[buf][(kb + t4) * 136 + wn + ni * 8 + g]);
                uint32_t b1 = __float_as_uint(Bs[buf][(kb + t4 + 4) * 136 + wn + ni * 8 + g]);
                mma8(acc[0][ni], af[0], b0, b1);
                mma8(acc[1][ni], af[1], b0, b1);
            }
        }
        if (more) {
            #pragma unroll
            for (int l = 0; l < 2; l++) {
                *(float4*)&As[buf ^ 1][(l * 64 + arow) * 20 + ac4] = pA[l];
                *(float4*)&Bs[buf ^ 1][(l * 8 + wid) * 136 + lane * 4] = pB[l];
            }
            __syncthreads();
            buf ^= 1;
        }
    }

    if (PROJ) {
        #pragma unroll
        for (int mi = 0; mi < 2; mi++)
            #pragma unroll
            for (int ni = 0; ni < 8; ni++)
                #pragma unroll
                for (int p = 0; p < 4; p++)
                    acc[mi][ni][p] = tf32r(acc[mi][ni][p]);
    }

    #pragma unroll
    for (int mi = 0; mi < 2; mi++) {
        #pragma unroll
        for (int ni = 0; ni < 8; ni++) {
            int col = bx * 128 + wn + ni * 8 + 2 * t4;
            float2 o0 = make_float2(acc[mi][ni][0], acc[mi][ni][1]);
            float2 o1 = make_float2(acc[mi][ni][2], acc[mi][ni][3]);
            if (!PROJ) {
                float2 bb = *(const float2*)(bias + col);
                o0.x += bb.x; o0.y += bb.y; o1.x += bb.x; o1.y += bb.y;
            }
            int r0 = grow + wm + mi * 16 + g;
            *(float2*)(C + (size_t)r0 * 512 + col) = o0;
            *(float2*)(C + (size_t)(r0 + 8) * 512 + col) = o1;
        }
    }

    if (PROJ && (grow >> 14) < 2) {
        int t = grow >> 14;
        int h = bx * 2 + (wid & 1);
        #pragma unroll
        for (int mi = 0; mi < 2; mi++) {
            #pragma unroll
            for (int half = 0; half < 2; half++) {
                float s = 0.f;
                #pragma unroll
                for (int ni = 0; ni < 8; ni++) {
                    float x = acc[mi][ni][2 * half], y = acc[mi][ni][2 * half + 1];
                    s += x * x + y * y;
                }
                s += __shfl_xor_sync(0xffffffffu, s, 1);
                s += __shfl_xor_sync(0xffffffffu, s, 2);
                if (t4 == 0) {
                    int gr = grow + wm + mi * 16 + g + 8 * half;
                    int r = gr & 16383, bb = r >> 8, n = r & 255;
                    g_norms[t * 131072 + (h * 64 + bb) * 256 + n] = sqrtf(s);
                }
            }
        }
    }
}

// ---------------- 3) chunk stats: raw Gram (tf32 mma) + rank-1 correction ----------------
__global__ __launch_bounds__(256) void stats_kernel()
{
    extern __shared__ float sE[];        // [256][72]
    __shared__ float red[256];
    __shared__ float smu[64];
    __shared__ float r3[3][8];

    int tid = threadIdx.x;
    int bx = blockIdx.x;
    int t = bx >> 9;
    int rest = bx & 511;
    int c = rest >> 3, s = rest & 7;
    int h = c >> 3, b = ((c & 7) << 3) + s;
    const float* base = g_f + (size_t)t * FS + (size_t)(b * 256) * 512 + h * 64;

    for (int idx = tid; idx < 4096; idx += 256) {
        int n = idx >> 4, c4 = (idx & 15) * 4;
        *(float4*)&sE[n * 72 + c4] = *(const float4*)(base + (size_t)n * 512 + c4);
    }
    __syncthreads();

    {
        int i = tid & 63, grp = tid >> 6;
        float sm = 0.f;
        #pragma unroll 8
        for (int n = grp; n < 256; n += 4) sm += sE[n * 72 + i];
        red[tid] = sm;
        __syncthreads();
        if (tid < 64)
            smu[tid] = (red[tid] + red[tid + 64] + red[tid + 128] + red[tid + 192]) * (1.f / 256.f);
        __syncthreads();
    }

    int lane = tid & 31, wid = tid >> 5;
    int g = lane >> 2, t4 = lane & 3;
    int wm = (wid & 3) * 16, wn = (wid >> 2) * 32;
    float gacc[4][4] = {};
    #pragma unroll 4
    for (int ks = 0; ks < 32; ks++) {
        int kb8 = ks * 8;
        uint32_t af[4];
        af[0] = __float_as_uint(sE[(kb8 + t4) * 72 + wm + g]);
        af[1] = __float_as_uint(sE[(kb8 + t4) * 72 + wm + g + 8]);
        af[2] = __float_as_uint(sE[(kb8 + t4 + 4) * 72 + wm + g]);
        af[3] = __float_as_uint(sE[(kb8 + t4 + 4) * 72 + wm + g + 8]);
        #pragma unroll
        for (int ni = 0; ni < 4; ni++) {
            uint32_t b0 = __float_as_uint(sE[(kb8 + t4) * 72 + wn + ni * 8 + g]);
            uint32_t b1 = __float_as_uint(sE[(kb8 + t4 + 4) * 72 + wn + ni * 8 + g]);
            mma8(gacc[ni], af, b0, b1);
        }
    }

    int row0 = wm + g, row1 = wm + g + 8;
    float mr0 = smu[row0] * 256.f, mr1 = smu[row1] * 256.f;
    float tot = 0.f, dsum = 0.f, vsum = 0.f;
    #pragma unroll
    for (int ni = 0; ni < 4; ni++) {
        int c0 = wn + ni * 8 + 2 * t4, c1 = c0 + 1;
        float mc0 = smu[c0], mc1 = smu[c1];
        float g00 = gacc[ni][0] - mr0 * mc0;
        float g01 = gacc[ni][1] - mr0 * mc1;
        float g10 = gacc[ni][2] - mr1 * mc0;
        float g11 = gacc[ni][3] - mr1 * mc1;
        tot += g00 * g00 + g01 * g01 + g10 * g10 + g11 * g11;
        if (row0 == c0) { dsum += g00 * g00; vsum += fmaxf(0.f, 1.f - sqrtf(g00 * (1.f / 255.f) + 1e-8f)); }
        if (row0 == c1) { dsum += g01 * g01; vsum += fmaxf(0.f, 1.f - sqrtf(g01 * (1.f / 255.f) + 1e-8f)); }
        if (row1 == c0) { dsum += g10 * g10; vsum += fmaxf(0.f, 1.f - sqrtf(g10 * (1.f / 255.f) + 1e-8f)); }
        if (row1 == c1) { dsum += g11 * g11; vsum += fmaxf(0.f, 1.f - sqrtf(g11 * (1.f / 255.f) + 1e-8f)); }
    }

    float a0 = warp_sum(tot), a1 = warp_sum(dsum), a2 = warp_sum(vsum);
    if (!lane) { r3[0][wid] = a0; r3[1][wid] = a1; r3[2][wid] = a2; }
    __syncthreads();
    if (tid == 0) {
        float T = 0.f, D = 0.f, V = 0.f;
        #pragma unroll
        for (int i = 0; i < 8; i++) { T += r3[0][i]; D += r3[1][i]; V += r3[2][i]; }
        g_part[bx * 2 + 0] = V * (1.f / 512.f);
        g_part[bx * 2 + 1] = (T - D) * (1.f / (255.f * 255.f * 64.f * 8.f));
    }
}

// ---------------- 4) fused attention (batch-major y for splitting) ----------------
__global__ __launch_bounds__(256) void attn_kernel(
    const float* __restrict__ cl, const float* __restrict__ vl, int yoff)
{
    extern __shared__ float sh[];
    float* Qs  = sh;                       // [128][68]
    float* Ks  = sh + 128 * 68;            // [64][68]
    float* Vs  = sh + 128 * 68 + 64 * 68;  // [64][72]
    float* Ssm = Vs + 64 * 72;             // [128][68]

    int tid = threadIdx.x, lane = tid & 31, wid = tid >> 5;
    int g = lane >> 2, t4 = lane & 3;
    int wm = (wid >> 1) * 32, wn = (wid & 1) * 32;
    int nt = blockIdx.x;
    int y = blockIdx.y + yoff;             // b*8 + h
    int h = y & 7, b = y >> 3;
    int hb = h * 64 + b;
    int c = h * 8 + (b >> 3);

    const float* qb = g_f + (size_t)(b * 256 + nt * 128) * 512 + h * 64;
    const float* kb = g_f + FS + (size_t)(b * 256) * 512 + h * 64;
    const float* vb = g_f + 2 * FS + (size_t)(b * 256) * 512 + h * 64;

    {
        int lrow = tid >> 4, lc4 = (tid & 15) * 4;
        #pragma unroll
        for (int l = 0; l < 8; l++) {
            int row = l * 16 + lrow;
            *(float4*)&Qs[row * 68 + lc4] = *(const float4*)(qb + (size_t)row * 512 + lc4);
        }
    }

    float cw = 1.f / (1.f + expf(-cl[0]));
    float vw = 1.f / (1.f + expf(-vl[0]));
    float cosw = 1.f - cw - vw;
    float Vq = 0.f, Cq = 0.f, Vk = 0.f, Ck = 0.f;
    #pragma unroll
    for (int s = 0; s < 8; s++) {
        Vq += g_part[(c * 8 + s) * 2];
        Cq += g_part[(c * 8 + s) * 2 + 1];
        Vk += g_part[(512 + c * 8 + s) * 2];
        Ck += g_part[(512 + c * 8 + s) * 2 + 1];
    }
    float biasv = cw * (Cq * Ck) + vw * (Vq * Vk);

    float qinv[2][2];
    #pragma unroll
    for (int mi = 0; mi < 2; mi++)
        #pragma unroll
        for (int half = 0; half < 2; half++) {
            int n = nt * 128 + wm + mi * 16 + g + 8 * half;
            qinv[mi][half] = cosw / g_norms[hb * 256 + n];
        }

    int krow = tid >> 2;
    int kc0 = (tid & 3) * 4;

    float oacc[2][4][4] = {};
    for (int mc = 0; mc < 4; mc++) {
        #pragma unroll
        for (int l = 0; l < 4; l++) {
            int col = kc0 + l * 16;
            *(float4*)&Ks[krow * 68 + col] =
                *(const float4*)(kb + (size_t)(mc * 64 + krow) * 512 + col);
            *(float4*)&Vs[krow * 72 + col] =
                *(const float4*)(vb + (size_t)(mc * 64 + krow) * 512 + col);
        }
        __syncthreads();

        float sacc[2][4][4] = {};
        #pragma unroll
        for (int ks = 0; ks < 8; ks++) {
            int kb8 = ks * 8;
            uint32_t af[2][4];
            #pragma unroll
            for (int mi = 0; mi < 2; mi++) {
                const float* ap = &Qs[(wm + mi * 16) * 68 + kb8];
                af[mi][0] = __float_as_uint(ap[g * 68 + t4]);
                af[mi][1] = __float_as_uint(ap[(g + 8) * 68 + t4]);
                af[mi][2] = __float_as_uint(ap[g * 68 + t4 + 4]);
                af[mi][3] = __float_as_uint(ap[(g + 8) * 68 + t4 + 4]);
            }
            #pragma unroll
            for (int ni = 0; ni < 4; ni++) {
                uint32_t b0 = __float_as_uint(Ks[(wn + ni * 8 + g) * 68 + kb8 + t4]);
                uint32_t b1 = __float_as_uint(Ks[(wn + ni * 8 + g) * 68 + kb8 + t4 + 4]);
                mma8(sacc[0][ni], af[0], b0, b1);
                mma8(sacc[1][ni], af[1], b0, b1);
            }
        }

        #pragma unroll
        for (int ni = 0; ni < 4; ni++) {
            int ml = wn + ni * 8 + 2 * t4;
            int m0 = mc * 64 + ml;
            float ki0 = 1.f / g_norms[131072 + hb * 256 + m0];
            float ki1 = 1.f / g_norms[131072 + hb * 256 + m0 + 1];
            #pragma unroll
            for (int mi = 0; mi < 2; mi++) {
                #pragma unroll
                for (int half = 0; half < 2; half++) {
                    int nl = wm + mi * 16 + g + 8 * half;
                    float2 o = make_float2(
                        tf32r(qinv[mi][half] * sacc[mi][ni][2 * half] * ki0 + biasv),
                        tf32r(qinv[mi][half] * sacc[mi][ni][2 * half + 1] * ki1 + biasv));
                    *(float2*)&Ssm[nl * 68 + ml] = o;
                }
            }
        }
        __syncthreads();

        #pragma unroll
        for (int ks = 0; ks < 8; ks++) {
            int kb8 = ks * 8;
            uint32_t af[2][4];
            #pragma unroll
            for (int mi = 0; mi < 2; mi++) {
                const float* ap = &Ssm[(wm + mi * 16) * 68 + kb8];
                af[mi][0] = __float_as_uint(ap[g * 68 + t4]);
                af[mi][1] = __float_as_uint(ap[(g + 8) * 68 + t4]);
                af[mi][2] = __float_as_uint(ap[g * 68 + t4 + 4]);
                af[mi][3] = __float_as_uint(ap[(g + 8) * 68 + t4 + 4]);
            }
            #pragma unroll
            for (int ni = 0; ni < 4; ni++) {
                uint32_t b0 = __float_as_uint(Vs[(kb8 + t4) * 72 + wn + ni * 8 + g]);
                uint32_t b1 = __float_as_uint(Vs[(kb8 + t4 + 4) * 72 + wn + ni * 8 + g]);
                mma8(oacc[0][ni], af[0], b0, b1);
                mma8(oacc[1][ni], af[1], b0, b1);
            }
        }
        __syncthreads();
    }

    #pragma unroll
    for (int mi = 0; mi < 2; mi++) {
        #pragma unroll
        for (int ni = 0; ni < 4; ni++) {
            int col = wn + ni * 8 + 2 * t4;
            int n0 = nt * 128 + wm + mi * 16 + g;
            *(float2*)(g_att + (size_t)(b * 256 + n0) * 512 + h * 64 + col) =
                make_float2(tf32r(oacc[mi][ni][0]), tf32r(oacc[mi][ni][1]));
            *(float2*)(g_att + (size_t)(b * 256 + n0 + 8) * 512 + h * 64 + col) =
                make_float2(tf32r(oacc[mi][ni][2]), tf32r(oacc[mi][ni][3]));
        }
    }
}

// ---------------- launch ----------------
extern "C" void kernel_launch(void* const* d_in, const int* in_sizes, int n_in,
                              void* d_out, int out_size)
{
    const float* q   = (const float*)d_in[0];
    const float* k   = (const float*)d_in[1];
    const float* v   = (const float*)d_in[2];
    const float* gma = (const float*)d_in[3];
    const float* bta = (const float*)d_in[4];
    const float* Win = (const float*)d_in[5];
    const float* Wout= (const float*)d_in[6];
    const float* bout= (const float*)d_in[7];
    const float* covl= (const float*)d_in[8];
    const float* varl= (const float*)d_in[9];
    float* out = (float*)d_out;

    void *pxn, *pf, *patt, *pwin, *pwout;
    cudaGetSymbolAddress(&pxn, g_xn);
    cudaGetSymbolAddress(&pf, g_f);
    cudaGetSymbolAddress(&patt, g_att);
    cudaGetSymbolAddress(&pwin, g_win);
    cudaGetSymbolAddress(&pwout, g_wout);

    constexpr int ATTN_SMEM  = (128 * 68 + 64 * 68 + 64 * 72 + 128 * 68) * 4;
    constexpr int STATS_SMEM = 256 * 72 * 4;

    static cudaStream_t s2;
    static cudaEvent_t evRoot, evW, evQK, evS, evA1, evO1;
    static bool init_done = false;
    if (!init_done) {
        cudaFuncSetAttribute(attn_kernel,  cudaFuncAttributeMaxDynamicSharedMemorySize, ATTN_SMEM);
        cudaFuncSetAttribute(stats_kernel, cudaFuncAttributeMaxDynamicSharedMemorySize, STATS_SMEM);
        cudaStreamCreateWithFlags(&s2, cudaStreamNonBlocking);
        cudaEventCreateWithFlags(&evRoot, cudaEventDisableTiming);
        cudaEventCreateWithFlags(&evW, cudaEventDisableTiming);
        cudaEventCreateWithFlags(&evQK, cudaEventDisableTiming);
        cudaEventCreateWithFlags(&evS, cudaEventDisableTiming);
        cudaEventCreateWithFlags(&evA1, cudaEventDisableTiming);
        cudaEventCreateWithFlags(&evO1, cudaEventDisableTiming);
        init_done = true;
    }

    // fork s2 from the capturing stream
    cudaEventRecord(evRoot, 0);
    cudaStreamWaitEvent(s2, evRoot, 0);

    // wround on s2 concurrent with ln on main
    wround_kernel<<<256, 256, 0, s2>>>(Win, Wout);
    cudaEventRecord(evW, s2);

    ln_kernel<<<6144, 256>>>(q, k, v, gma, bta);
    cudaStreamWaitEvent(0, evW, 0);

    // proj q,k rows
    mm_kernel<true><<<dim3(4, 256), 256>>>((const float*)pxn, (const float*)pwin,
                                           (float*)pf, nullptr, 0);
    cudaEventRecord(evQK, 0);

    // stats on s2, concurrent with proj_v
    cudaStreamWaitEvent(s2, evQK, 0);
    stats_kernel<<<1024, 256, STATS_SMEM, s2>>>();
    cudaEventRecord(evS, s2);

    // proj v rows on main
    mm_kernel<true><<<dim3(4, 128), 256>>>((const float*)pxn, (const float*)pwin,
                                           (float*)pf, nullptr, 256);

    // join stats, then attention first half (b 0..31)
    cudaStreamWaitEvent(0, evS, 0);
    attn_kernel<<<dim3(2, 256), 256, ATTN_SMEM>>>(covl, varl, 0);
    cudaEventRecord(evA1, 0);

    // out-GEMM rows 0..8191 on s2, concurrent with attn second half
    cudaStreamWaitEvent(s2, evA1, 0);
    mm_kernel<false><<<dim3(4, 64), 256, 0, s2>>>((const float*)patt, (const float*)pwout,
                                                  out, bout, 0);
    cudaEventRecord(evO1, s2);

    // attention second half (b 32..63) on main
    attn_kernel<<<dim3(2, 256), 256, ATTN_SMEM>>>(covl, varl, 256);

    // out-GEMM rows 8192..16383 on main
    mm_kernel<false><<<dim3(4, 64), 256>>>((const float*)patt, (const float*)pwout,
                                           out, bout, 64);

    // join s2 back before capture ends
    cudaStreamWaitEvent(0, evO1, 0);
}

// round 12
// speedup vs baseline: 1.1088x; 1.0481x over previous
#include <cuda_runtime.h>
#include <math.h>
#include <stdint.h>

constexpr size_t FS = (size_t)16384 * 512;

__device__ float g_xn[3 * FS];                      // LN output (tf32-rounded)
__device__ float g_f[3 * FS];                       // projected features (tf32-rounded)
__device__ float g_att[FS];                         // attention out (tf32-rounded)
__device__ float g_win[512 * 512];
__device__ float g_wout[512 * 512];
__device__ float g_norms[2 * 512 * 256];            // qn,kn [t][hb][n]
__device__ float g_part[2048];                      // stats partials [t][c][s][2]

__device__ __forceinline__ float warp_sum(float v) {
    #pragma unroll
    for (int o = 16; o; o >>= 1) v += __shfl_xor_sync(0xffffffffu, v, o);
    return v;
}
__device__ __forceinline__ float tf32r(float x) {
    uint32_t u;
    asm("cvt.rna.tf32.f32 %0, %1;" : "=r"(u) : "f"(x));
    return __uint_as_float(u);
}
__device__ __forceinline__ void mma8(float c[4], const uint32_t a[4], uint32_t b0, uint32_t b1) {
    asm volatile(
        "mma.sync.aligned.m16n8k8.row.col.f32.tf32.tf32.f32 "
        "{%0,%1,%2,%3},{%4,%5,%6,%7},{%8,%9},{%0,%1,%2,%3};"
        : "+f"(c[0]), "+f"(c[1]), "+f"(c[2]), "+f"(c[3])
        : "r"(a[0]), "r"(a[1]), "r"(a[2]), "r"(a[3]), "r"(b0), "r"(b1));
}

// ---------------- 0) round weights once ----------------
__global__ __launch_bounds__(256) void wround_kernel(
    const float* __restrict__ Win, const float* __restrict__ Wout)
{
    int idx = (blockIdx.x * 256 + threadIdx.x) * 4;
    float4 a = *(const float4*)(Win + idx);
    a.x = tf32r(a.x); a.y = tf32r(a.y); a.z = tf32r(a.z); a.w = tf32r(a.w);
    *(float4*)(g_win + idx) = a;
    float4 b = *(const float4*)(Wout + idx);
    b.x = tf32r(b.x); b.y = tf32r(b.y); b.z = tf32r(b.z); b.w = tf32r(b.w);
    *(float4*)(g_wout + idx) = b;
}

// ---------------- 1) LayerNorm, writes tf32-rounded output (+ block offset) ----------------
__global__ __launch_bounds__(256) void ln_kernel(
    const float* __restrict__ q, const float* __restrict__ k, const float* __restrict__ v,
    const float* __restrict__ gma, const float* __restrict__ bta, int blockoff)
{
    int warp = threadIdx.x >> 5, lane = threadIdx.x & 31;
    int row = (blockIdx.x + blockoff) * 8 + warp;
    int t = row >> 14, r = row & 16383;
    const float* src = (t == 0 ? q : (t == 1 ? k : v)) + (size_t)r * 512;
    float x[16], s = 0.f;
    #pragma unroll
    for (int i = 0; i < 16; i++) { x[i] = src[lane + 32 * i]; s += x[i]; }
    s = warp_sum(s);
    float mu = s * (1.f / 512.f), ss = 0.f;
    #pragma unroll
    for (int i = 0; i < 16; i++) { float d = x[i] - mu; ss += d * d; }
    ss = warp_sum(ss);
    float rs = rsqrtf(ss * (1.f / 512.f) + 1e-5f);
    float* dst = g_xn + (size_t)row * 512;
    #pragma unroll
    for (int i = 0; i < 16; i++) {
        int c = lane + 32 * i;
        dst[c] = tf32r((x[i] - mu) * rs * gma[c] + bta[c]);
    }
}

// ---------------- 2/6) tf32 GEMM 128x128, BK=16 (known good) + rowoff ----------------
template<bool PROJ>
__global__ __launch_bounds__(256) void mm_kernel(
    const float* __restrict__ A, const float* __restrict__ B,
    float* __restrict__ C, const float* __restrict__ bias, int rowoff)
{
    __shared__ float As[2][128 * 20];
    __shared__ float Bs[2][16 * 136];

    int tid = threadIdx.x, lane = tid & 31, wid = tid >> 5;
    int g = lane >> 2, t4 = lane & 3;
    int wm = (wid >> 1) * 32, wn = (wid & 1) * 64;
    int bx = blockIdx.x;
    int grow = (blockIdx.y + rowoff) * 128;

    int arow = tid >> 2, ac4 = (tid & 3) * 4;
    const float* srcA[2];
    #pragma unroll
    for (int l = 0; l < 2; l++)
        srcA[l] = A + (size_t)(grow + l * 64 + arow) * 512;
    const float* Bbase = B + (size_t)bx * 128 + lane * 4;

    float acc[2][8][4] = {};
    float4 pA[2], pB[2];

    #pragma unroll
    for (int l = 0; l < 2; l++) {
        *(float4*)&As[0][(l * 64 + arow) * 20 + ac4] = *(const float4*)(srcA[l] + ac4);
        *(float4*)&Bs[0][(l * 8 + wid) * 136 + lane * 4] =
            *(const float4*)(Bbase + (size_t)(l * 8 + wid) * 512);
    }
    __syncthreads();

    int buf = 0;
    for (int bk = 0; bk < 512; bk += 16) {
        bool more = (bk + 16) < 512;
        if (more) {
            #pragma unroll
            for (int l = 0; l < 2; l++) {
                pA[l] = *(const float4*)(srcA[l] + bk + 16 + ac4);
                pB[l] = *(const float4*)(Bbase + (size_t)(bk + 16 + l * 8 + wid) * 512);
            }
        }
        #pragma unroll
        for (int ks = 0; ks < 2; ks++) {
            int kb = ks * 8;
            uint32_t af[2][4];
            #pragma unroll
            for (int mi = 0; mi < 2; mi++) {
                const float* ap = &As[buf][(wm + mi * 16) * 20 + kb];
                af[mi][0] = __float_as_uint(ap[g * 20 + t4]);
                af[mi][1] = __float_as_uint(ap[(g + 8) * 20 + t4]);
                af[mi][2] = __float_as_uint(ap[g * 20 + t4 + 4]);
                af[mi][3] = __float_as_uint(ap[(g + 8) * 20 + t4 + 4]);
            }
            #pragma unroll
            for (int ni = 0; ni < 8; ni++) {
                uint32_t b0 = __float_as_uint(Bs[buf][(kb + t4) * 136 + wn + ni * 8 + g]);
                uint32_t b1 = __float_as_uint(Bs[buf][(kb + t4 + 4) * 136 + wn + ni * 8 + g]);
                mma8(acc[0][ni], af[0], b0, b1);
                mma8(acc[1][ni], af[1], b0, b1);
            }
        }
        if (more) {
            #pragma unroll
            for (int l = 0; l < 2; l++) {
                *(float4*)&As[buf ^ 1][(l * 64 + arow) * 20 + ac4] = pA[l];
                *(float4*)&Bs[buf ^ 1][(l * 8 + wid) * 136 + lane * 4] = pB[l];
            }
            __syncthreads();
            buf ^= 1;
        }
    }

    if (PROJ) {
        #pragma unroll
        for (int mi = 0; mi < 2; mi++)
            #pragma unroll
            for (int ni = 0; ni < 8; ni++)
                #pragma unroll
                for (int p = 0; p < 4; p++)
                    acc[mi][ni][p] = tf32r(acc[mi][ni][p]);
    }

    #pragma unroll
    for (int mi = 0; mi < 2; mi++) {
        #pragma unroll
        for (int ni = 0; ni < 8; ni++) {
            int col = bx * 128 + wn + ni * 8 + 2 * t4;
            float2 o0 = make_float2(acc[mi][ni][0], acc[mi][ni][1]);
            float2 o1 = make_float2(acc[mi][ni][2], acc[mi][ni][3]);
            if (!PROJ) {
                float2 bb = *(const float2*)(bias + col);
                o0.x += bb.x; o0.y += bb.y; o1.x += bb.x; o1.y += bb.y;
            }
            int r0 = grow + wm + mi * 16 + g;
            *(float2*)(C + (size_t)r0 * 512 + col) = o0;
            *(float2*)(C + (size_t)(r0 + 8) * 512 + col) = o1;
        }
    }

    if (PROJ && (grow >> 14) < 2) {
        int t = grow >> 14;
        int h = bx * 2 + (wid & 1);
        #pragma unroll
        for (int mi = 0; mi < 2; mi++) {
            #pragma unroll
            for (int half = 0; half < 2; half++) {
                float s = 0.f;
                #pragma unroll
                for (int ni = 0; ni < 8; ni++) {
                    float x = acc[mi][ni][2 * half], y = acc[mi][ni][2 * half + 1];
                    s += x * x + y * y;
                }
                s += __shfl_xor_sync(0xffffffffu, s, 1);
                s += __shfl_xor_sync(0xffffffffu, s, 2);
                if (t4 == 0) {
                    int gr = grow + wm + mi * 16 + g + 8 * half;
                    int r = gr & 16383, bb = r >> 8, n = r & 255;
                    g_norms[t * 131072 + (h * 64 + bb) * 256 + n] = sqrtf(s);
                }
            }
        }
    }
}

// ---------------- 3) chunk stats: raw Gram (tf32 mma) + rank-1 correction ----------------
__global__ __launch_bounds__(256) void stats_kernel()
{
    extern __shared__ float sE[];        // [256][72]
    __shared__ float red[256];
    __shared__ float smu[64];
    __shared__ float r3[3][8];

    int tid = threadIdx.x;
    int bx = blockIdx.x;
    int t = bx >> 9;
    int rest = bx & 511;
    int c = rest >> 3, s = rest & 7;
    int h = c >> 3, b = ((c & 7) << 3) + s;
    const float* base = g_f + (size_t)t * FS + (size_t)(b * 256) * 512 + h * 64;

    for (int idx = tid; idx < 4096; idx += 256) {
        int n = idx >> 4, c4 = (idx & 15) * 4;
        *(float4*)&sE[n * 72 + c4] = *(const float4*)(base + (size_t)n * 512 + c4);
    }
    __syncthreads();

    {
        int i = tid & 63, grp = tid >> 6;
        float sm = 0.f;
        #pragma unroll 8
        for (int n = grp; n < 256; n += 4) sm += sE[n * 72 + i];
        red[tid] = sm;
        __syncthreads();
        if (tid < 64)
            smu[tid] = (red[tid] + red[tid + 64] + red[tid + 128] + red[tid + 192]) * (1.f / 256.f);
        __syncthreads();
    }

    int lane = tid & 31, wid = tid >> 5;
    int g = lane >> 2, t4 = lane & 3;
    int wm = (wid & 3) * 16, wn = (wid >> 2) * 32;
    float gacc[4][4] = {};
    #pragma unroll 4
    for (int ks = 0; ks < 32; ks++) {
        int kb8 = ks * 8;
        uint32_t af[4];
        af[0] = __float_as_uint(sE[(kb8 + t4) * 72 + wm + g]);
        af[1] = __float_as_uint(sE[(kb8 + t4) * 72 + wm + g + 8]);
        af[2] = __float_as_uint(sE[(kb8 + t4 + 4) * 72 + wm + g]);
        af[3] = __float_as_uint(sE[(kb8 + t4 + 4) * 72 + wm + g + 8]);
        #pragma unroll
        for (int ni = 0; ni < 4; ni++) {
            uint32_t b0 = __float_as_uint(sE[(kb8 + t4) * 72 + wn + ni * 8 + g]);
            uint32_t b1 = __float_as_uint(sE[(kb8 + t4 + 4) * 72 + wn + ni * 8 + g]);
            mma8(gacc[ni], af, b0, b1);
        }
    }

    int row0 = wm + g, row1 = wm + g + 8;
    float mr0 = smu[row0] * 256.f, mr1 = smu[row1] * 256.f;
    float tot = 0.f, dsum = 0.f, vsum = 0.f;
    #pragma unroll
    for (int ni = 0; ni < 4; ni++) {
        int c0 = wn + ni * 8 + 2 * t4, c1 = c0 + 1;
        float mc0 = smu[c0], mc1 = smu[c1];
        float g00 = gacc[ni][0] - mr0 * mc0;
        float g01 = gacc[ni][1] - mr0 * mc1;
        float g10 = gacc[ni][2] - mr1 * mc0;
        float g11 = gacc[ni][3] - mr1 * mc1;
        tot += g00 * g00 + g01 * g01 + g10 * g10 + g11 * g11;
        if (row0 == c0) { dsum += g00 * g00; vsum += fmaxf(0.f, 1.f - sqrtf(g00 * (1.f / 255.f) + 1e-8f)); }
        if (row0 == c1) { dsum += g01 * g01; vsum += fmaxf(0.f, 1.f - sqrtf(g01 * (1.f / 255.f) + 1e-8f)); }
        if (row1 == c0) { dsum += g10 * g10; vsum += fmaxf(0.f, 1.f - sqrtf(g10 * (1.f / 255.f) + 1e-8f)); }
        if (row1 == c1) { dsum += g11 * g11; vsum += fmaxf(0.f, 1.f - sqrtf(g11 * (1.f / 255.f) + 1e-8f)); }
    }

    float a0 = warp_sum(tot), a1 = warp_sum(dsum), a2 = warp_sum(vsum);
    if (!lane) { r3[0][wid] = a0; r3[1][wid] = a1; r3[2][wid] = a2; }
    __syncthreads();
    if (tid == 0) {
        float T = 0.f, D = 0.f, V = 0.f;
        #pragma unroll
        for (int i = 0; i < 8; i++) { T += r3[0][i]; D += r3[1][i]; V += r3[2][i]; }
        g_part[bx * 2 + 0] = V * (1.f / 512.f);
        g_part[bx * 2 + 1] = (T - D) * (1.f / (255.f * 255.f * 64.f * 8.f));
    }
}

// ---------------- 4) fused attention (unified grid, round-9 form) ----------------
__global__ __launch_bounds__(256) void attn_kernel(
    const float* __restrict__ cl, const float* __restrict__ vl)
{
    extern __shared__ float sh[];
    float* Qs  = sh;                       // [128][68]
    float* Ks  = sh + 128 * 68;            // [64][68]
    float* Vs  = sh + 128 * 68 + 64 * 68;  // [64][72]
    float* Ssm = Vs + 64 * 72;             // [128][68]

    int tid = threadIdx.x, lane = tid & 31, wid = tid >> 5;
    int g = lane >> 2, t4 = lane & 3;
    int wm = (wid >> 1) * 32, wn = (wid & 1) * 32;
    int nt = blockIdx.x, hb = blockIdx.y;
    int h = hb >> 6, b = hb & 63, c = hb >> 3;

    const float* qb = g_f + (size_t)(b * 256 + nt * 128) * 512 + h * 64;
    const float* kb = g_f + FS + (size_t)(b * 256) * 512 + h * 64;
    const float* vb = g_f + 2 * FS + (size_t)(b * 256) * 512 + h * 64;

    {
        int lrow = tid >> 4, lc4 = (tid & 15) * 4;
        #pragma unroll
        for (int l = 0; l < 8; l++) {
            int row = l * 16 + lrow;
            *(float4*)&Qs[row * 68 + lc4] = *(const float4*)(qb + (size_t)row * 512 + lc4);
        }
    }

    float cw = 1.f / (1.f + expf(-cl[0]));
    float vw = 1.f / (1.f + expf(-vl[0]));
    float cosw = 1.f - cw - vw;
    float Vq = 0.f, Cq = 0.f, Vk = 0.f, Ck = 0.f;
    #pragma unroll
    for (int s = 0; s < 8; s++) {
        Vq += g_part[(c * 8 + s) * 2];
        Cq += g_part[(c * 8 + s) * 2 + 1];
        Vk += g_part[(512 + c * 8 + s) * 2];
        Ck += g_part[(512 + c * 8 + s) * 2 + 1];
    }
    float biasv = cw * (Cq * Ck) + vw * (Vq * Vk);

    float qinv[2][2];
    #pragma unroll
    for (int mi = 0; mi < 2; mi++)
        #pragma unroll
        for (int half = 0; half < 2; half++) {
            int n = nt * 128 + wm + mi * 16 + g + 8 * half;
            qinv[mi][half] = cosw / g_norms[hb * 256 + n];
        }

    int krow = tid >> 2;
    int kc0 = (tid & 3) * 4;

    float oacc[2][4][4] = {};
    for (int mc = 0; mc < 4; mc++) {
        #pragma unroll
        for (int l = 0; l < 4; l++) {
            int col = kc0 + l * 16;
            *(float4*)&Ks[krow * 68 + col] =
                *(const float4*)(kb + (size_t)(mc * 64 + krow) * 512 + col);
            *(float4*)&Vs[krow * 72 + col] =
                *(const float4*)(vb + (size_t)(mc * 64 + krow) * 512 + col);
        }
        __syncthreads();

        float sacc[2][4][4] = {};
        #pragma unroll
        for (int ks = 0; ks < 8; ks++) {
            int kb8 = ks * 8;
            uint32_t af[2][4];
            #pragma unroll
            for (int mi = 0; mi < 2; mi++) {
                const float* ap = &Qs[(wm + mi * 16) * 68 + kb8];
                af[mi][0] = __float_as_uint(ap[g * 68 + t4]);
                af[mi][1] = __float_as_uint(ap[(g + 8) * 68 + t4]);
                af[mi][2] = __float_as_uint(ap[g * 68 + t4 + 4]);
                af[mi][3] = __float_as_uint(ap[(g + 8) * 68 + t4 + 4]);
            }
            #pragma unroll
            for (int ni = 0; ni < 4; ni++) {
                uint32_t b0 = __float_as_uint(Ks[(wn + ni * 8 + g) * 68 + kb8 + t4]);
                uint32_t b1 = __float_as_uint(Ks[(wn + ni * 8 + g) * 68 + kb8 + t4 + 4]);
                mma8(sacc[0][ni], af[0], b0, b1);
                mma8(sacc[1][ni], af[1], b0, b1);
            }
        }

        #pragma unroll
        for (int ni = 0; ni < 4; ni++) {
            int ml = wn + ni * 8 + 2 * t4;
            int m0 = mc * 64 + ml;
            float ki0 = 1.f / g_norms[131072 + hb * 256 + m0];
            float ki1 = 1.f / g_norms[131072 + hb * 256 + m0 + 1];
            #pragma unroll
            for (int mi = 0; mi < 2; mi++) {
                #pragma unroll
                for (int half = 0; half < 2; half++) {
                    int nl = wm + mi * 16 + g + 8 * half;
                    float2 o = make_float2(
                        tf32r(qinv[mi][half] * sacc[mi][ni][2 * half] * ki0 + biasv),
                        tf32r(qinv[mi][half] * sacc[mi][ni][2 * half + 1] * ki1 + biasv));
                    *(float2*)&Ssm[nl * 68 + ml] = o;
                }
            }
        }
        __syncthreads();

        #pragma unroll
        for (int ks = 0; ks < 8; ks++) {
            int kb8 = ks * 8;
            uint32_t af[2][4];
            #pragma unroll
            for (int mi = 0; mi < 2; mi++) {
                const float* ap = &Ssm[(wm + mi * 16) * 68 + kb8];
                af[mi][0] = __float_as_uint(ap[g * 68 + t4]);
                af[mi][1] = __float_as_uint(ap[(g + 8) * 68 + t4]);
                af[mi][2] = __float_as_uint(ap[g * 68 + t4 + 4]);
                af[mi][3] = __float_as_uint(ap[(g + 8) * 68 + t4 + 4]);
            }
            #pragma unroll
            for (int ni = 0; ni < 4; ni++) {
                uint32_t b0 = __float_as_uint(Vs[(kb8 + t4) * 72 + wn + ni * 8 + g]);
                uint32_t b1 = __float_as_uint(Vs[(kb8 + t4 + 4) * 72 + wn + ni * 8 + g]);
                mma8(oacc[0][ni], af[0], b0, b1);
                mma8(oacc[1][ni], af[1], b0, b1);
            }
        }
        __syncthreads();
    }

    #pragma unroll
    for (int mi = 0; mi < 2; mi++) {
        #pragma unroll
        for (int ni = 0; ni < 4; ni++) {
            int col = wn + ni * 8 + 2 * t4;
            int n0 = nt * 128 + wm + mi * 16 + g;
            *(float2*)(g_att + (size_t)(b * 256 + n0) * 512 + h * 64 + col) =
                make_float2(tf32r(oacc[mi][ni][0]), tf32r(oacc[mi][ni][1]));
            *(float2*)(g_att + (size_t)(b * 256 + n0 + 8) * 512 + h * 64 + col) =
                make_float2(tf32r(oacc[mi][ni][2]), tf32r(oacc[mi][ni][3]));
        }
    }
}

// ---------------- launch ----------------
extern "C" void kernel_launch(void* const* d_in, const int* in_sizes, int n_in,
                              void* d_out, int out_size)
{
    const float* q   = (const float*)d_in[0];
    const float* k   = (const float*)d_in[1];
    const float* v   = (const float*)d_in[2];
    const float* gma = (const float*)d_in[3];
    const float* bta = (const float*)d_in[4];
    const float* Win = (const float*)d_in[5];
    const float* Wout= (const float*)d_in[6];
    const float* bout= (const float*)d_in[7];
    const float* covl= (const float*)d_in[8];
    const float* varl= (const float*)d_in[9];
    float* out = (float*)d_out;

    void *pxn, *pf, *patt, *pwin, *pwout;
    cudaGetSymbolAddress(&pxn, g_xn);
    cudaGetSymbolAddress(&pf, g_f);
    cudaGetSymbolAddress(&patt, g_att);
    cudaGetSymbolAddress(&pwin, g_win);
    cudaGetSymbolAddress(&pwout, g_wout);

    constexpr int ATTN_SMEM  = (128 * 68 + 64 * 68 + 64 * 72 + 128 * 68) * 4;
    constexpr int STATS_SMEM = 256 * 72 * 4;

    static cudaStream_t s2;
    static cudaEvent_t evRoot, evW, evV, evQK, evS;
    static bool init_done = false;
    if (!init_done) {
        cudaFuncSetAttribute(attn_kernel,  cudaFuncAttributeMaxDynamicSharedMemorySize, ATTN_SMEM);
        cudaFuncSetAttribute(stats_kernel, cudaFuncAttributeMaxDynamicSharedMemorySize, STATS_SMEM);
        cudaStreamCreateWithFlags(&s2, cudaStreamNonBlocking);
        cudaEventCreateWithFlags(&evRoot, cudaEventDisableTiming);
        cudaEventCreateWithFlags(&evW, cudaEventDisableTiming);
        cudaEventCreateWithFlags(&evV, cudaEventDisableTiming);
        cudaEventCreateWithFlags(&evQK, cudaEventDisableTiming);
        cudaEventCreateWithFlags(&evS, cudaEventDisableTiming);
        init_done = true;
    }

    // fork s2 from the capturing stream
    cudaEventRecord(evRoot, 0);
    cudaStreamWaitEvent(s2, evRoot, 0);

    // s2: wround, then ln for v rows (both off the critical path)
    wround_kernel<<<256, 256, 0, s2>>>(Win, Wout);
    cudaEventRecord(evW, s2);
    ln_kernel<<<2048, 256, 0, s2>>>(q, k, v, gma, bta, 4096);   // v rows
    cudaEventRecord(evV, s2);

    // main: ln for q,k rows
    ln_kernel<<<4096, 256>>>(q, k, v, gma, bta, 0);
    cudaStreamWaitEvent(0, evW, 0);

    // proj q,k rows
    mm_kernel<true><<<dim3(4, 256), 256>>>((const float*)pxn, (const float*)pwin,
                                           (float*)pf, nullptr, 0);
    cudaEventRecord(evQK, 0);

    // stats on s2, concurrent with proj_v
    cudaStreamWaitEvent(s2, evQK, 0);
    stats_kernel<<<1024, 256, STATS_SMEM, s2>>>();
    cudaEventRecord(evS, s2);

    // proj v rows on main (needs ln_v done)
    cudaStreamWaitEvent(0, evV, 0);
    mm_kernel<true><<<dim3(4, 128), 256>>>((const float*)pxn, (const float*)pwin,
                                           (float*)pf, nullptr, 256);

    // join stats, then unified attention
    cudaStreamWaitEvent(0, evS, 0);
    attn_kernel<<<dim3(2, 512), 256, ATTN_SMEM>>>(covl, varl);

    // output GEMM
    mm_kernel<false><<<dim3(4, 128), 256>>>((const float*)patt, (const float*)pwout,
                                            out, bout, 0);
}

// round 13
// speedup vs baseline: 1.1254x; 1.0150x over previous
#include <cuda_runtime.h>
#include <math.h>
#include <stdint.h>

constexpr size_t FS = (size_t)16384 * 512;

__device__ float g_xn[3 * FS];                      // LN output (tf32-rounded)
__device__ float g_f[3 * FS];                       // projected features (tf32-rounded)
__device__ float g_att[FS];                         // attention out (tf32-rounded)
__device__ float g_win[512 * 512];
__device__ float g_wout[512 * 512];
__device__ float g_norms[2 * 512 * 256];            // qn,kn [t][hb][n]
__device__ float g_part[2048];                      // stats partials [t][c][s][2]

__device__ __forceinline__ float warp_sum(float v) {
    #pragma unroll
    for (int o = 16; o; o >>= 1) v += __shfl_xor_sync(0xffffffffu, v, o);
    return v;
}
__device__ __forceinline__ float tf32r(float x) {
    uint32_t u;
    asm("cvt.rna.tf32.f32 %0, %1;" : "=r"(u) : "f"(x));
    return __uint_as_float(u);
}
__device__ __forceinline__ void mma8(float c[4], const uint32_t a[4], uint32_t b0, uint32_t b1) {
    asm volatile(
        "mma.sync.aligned.m16n8k8.row.col.f32.tf32.tf32.f32 "
        "{%0,%1,%2,%3},{%4,%5,%6,%7},{%8,%9},{%0,%1,%2,%3};"
        : "+f"(c[0]), "+f"(c[1]), "+f"(c[2]), "+f"(c[3])
        : "r"(a[0]), "r"(a[1]), "r"(a[2]), "r"(a[3]), "r"(b0), "r"(b1));
}

// ---------------- 0) round weights once ----------------
__global__ __launch_bounds__(256) void wround_kernel(
    const float* __restrict__ Win, const float* __restrict__ Wout)
{
    int idx = (blockIdx.x * 256 + threadIdx.x) * 4;
    float4 a = *(const float4*)(Win + idx);
    a.x = tf32r(a.x); a.y = tf32r(a.y); a.z = tf32r(a.z); a.w = tf32r(a.w);
    *(float4*)(g_win + idx) = a;
    float4 b = *(const float4*)(Wout + idx);
    b.x = tf32r(b.x); b.y = tf32r(b.y); b.z = tf32r(b.z); b.w = tf32r(b.w);
    *(float4*)(g_wout + idx) = b;
}

// ---------------- 1) LayerNorm, writes tf32-rounded output (+ block offset) ----------------
__global__ __launch_bounds__(256) void ln_kernel(
    const float* __restrict__ q, const float* __restrict__ k, const float* __restrict__ v,
    const float* __restrict__ gma, const float* __restrict__ bta, int blockoff)
{
    int warp = threadIdx.x >> 5, lane = threadIdx.x & 31;
    int row = (blockIdx.x + blockoff) * 8 + warp;
    int t = row >> 14, r = row & 16383;
    const float* src = (t == 0 ? q : (t == 1 ? k : v)) + (size_t)r * 512;
    float x[16], s = 0.f;
    #pragma unroll
    for (int i = 0; i < 16; i++) { x[i] = src[lane + 32 * i]; s += x[i]; }
    s = warp_sum(s);
    float mu = s * (1.f / 512.f), ss = 0.f;
    #pragma unroll
    for (int i = 0; i < 16; i++) { float d = x[i] - mu; ss += d * d; }
    ss = warp_sum(ss);
    float rs = rsqrtf(ss * (1.f / 512.f) + 1e-5f);
    float* dst = g_xn + (size_t)row * 512;
    #pragma unroll
    for (int i = 0; i < 16; i++) {
        int c = lane + 32 * i;
        dst[c] = tf32r((x[i] - mu) * rs * gma[c] + bta[c]);
    }
}

// ---------------- 2/6) tf32 GEMM 128x128, 4 warps of 64x64, BK=16 ----------------
template<bool PROJ>
__global__ __launch_bounds__(128) void mm_kernel(
    const float* __restrict__ A, const float* __restrict__ B,
    float* __restrict__ C, const float* __restrict__ bias, int rowoff)
{
    __shared__ float As[2][128 * 20];
    __shared__ float Bs[2][16 * 136];

    int tid = threadIdx.x, lane = tid & 31, wid = tid >> 5;   // wid 0..3
    int g = lane >> 2, t4 = lane & 3;
    int wm = (wid >> 1) * 64, wn = (wid & 1) * 64;            // warp tile 64x64
    int bx = blockIdx.x;
    int grow = (blockIdx.y + rowoff) * 128;

    int arow = tid >> 2, ac4 = (tid & 3) * 4;                 // arow 0..31
    const float* srcA[4];
    #pragma unroll
    for (int l = 0; l < 4; l++)
        srcA[l] = A + (size_t)(grow + l * 32 + arow) * 512;
    int brow = tid >> 5, bcol = (tid & 31) * 4;               // brow 0..3
    const float* Bbase = B + (size_t)bx * 128 + bcol;

    float acc[4][8][4] = {};
    float4 pA[4], pB[4];

    #pragma unroll
    for (int l = 0; l < 4; l++) {
        *(float4*)&As[0][(l * 32 + arow) * 20 + ac4] = *(const float4*)(srcA[l] + ac4);
        *(float4*)&Bs[0][(l * 4 + brow) * 136 + bcol] =
            *(const float4*)(Bbase + (size_t)(l * 4 + brow) * 512);
    }
    __syncthreads();

    int buf = 0;
    for (int bk = 0; bk < 512; bk += 16) {
        bool more = (bk + 16) < 512;
        if (more) {
            #pragma unroll
            for (int l = 0; l < 4; l++) {
                pA[l] = *(const float4*)(srcA[l] + bk + 16 + ac4);
                pB[l] = *(const float4*)(Bbase + (size_t)(bk + 16 + l * 4 + brow) * 512);
            }
        }
        #pragma unroll
        for (int ks = 0; ks < 2; ks++) {
            int kb = ks * 8;
            uint32_t af[4][4];
            #pragma unroll
            for (int mi = 0; mi < 4; mi++) {
                const float* ap = &As[buf][(wm + mi * 16) * 20 + kb];
                af[mi][0] = __float_as_uint(ap[g * 20 + t4]);
                af[mi][1] = __float_as_uint(ap[(g + 8) * 20 + t4]);
                af[mi][2] = __float_as_uint(ap[g * 20 + t4 + 4]);
                af[mi][3] = __float_as_uint(ap[(g + 8) * 20 + t4 + 4]);
            }
            #pragma unroll
            for (int ni = 0; ni < 8; ni++) {
                uint32_t b0 = __float_as_uint(Bs[buf][(kb + t4) * 136 + wn + ni * 8 + g]);
                uint32_t b1 = __float_as_uint(Bs[buf][(kb + t4 + 4) * 136 + wn + ni * 8 + g]);
                #pragma unroll
                for (int mi = 0; mi < 4; mi++)
                    mma8(acc[mi][ni], af[mi], b0, b1);
            }
        }
        if (more) {
            #pragma unroll
            for (int l = 0; l < 4; l++) {
                *(float4*)&As[buf ^ 1][(l * 32 + arow) * 20 + ac4] = pA[l];
                *(float4*)&Bs[buf ^ 1][(l * 4 + brow) * 136 + bcol] = pB[l];
            }
            __syncthreads();
            buf ^= 1;
        }
    }

    if (PROJ) {
        #pragma unroll
        for (int mi = 0; mi < 4; mi++)
            #pragma unroll
            for (int ni = 0; ni < 8; ni++)
                #pragma unroll
                for (int p = 0; p < 4; p++)
                    acc[mi][ni][p] = tf32r(acc[mi][ni][p]);
    }

    #pragma unroll
    for (int mi = 0; mi < 4; mi++) {
        #pragma unroll
        for (int ni = 0; ni < 8; ni++) {
            int col = bx * 128 + wn + ni * 8 + 2 * t4;
            float2 o0 = make_float2(acc[mi][ni][0], acc[mi][ni][1]);
            float2 o1 = make_float2(acc[mi][ni][2], acc[mi][ni][3]);
            if (!PROJ) {
                float2 bb = *(const float2*)(bias + col);
                o0.x += bb.x; o0.y += bb.y; o1.x += bb.x; o1.y += bb.y;
            }
            int r0 = grow + wm + mi * 16 + g;
            *(float2*)(C + (size_t)r0 * 512 + col) = o0;
            *(float2*)(C + (size_t)(r0 + 8) * 512 + col) = o1;
        }
    }

    if (PROJ && (grow >> 14) < 2) {
        int t = grow >> 14;
        int h = bx * 2 + (wid & 1);       // warp N-tile (64) == one head span
        #pragma unroll
        for (int mi = 0; mi < 4; mi++) {
            #pragma unroll
            for (int half = 0; half < 2; half++) {
                float s = 0.f;
                #pragma unroll
                for (int ni = 0; ni < 8; ni++) {
                    float x = acc[mi][ni][2 * half], y = acc[mi][ni][2 * half + 1];
                    s += x * x + y * y;
                }
                s += __shfl_xor_sync(0xffffffffu, s, 1);
                s += __shfl_xor_sync(0xffffffffu, s, 2);
                if (t4 == 0) {
                    int gr = grow + wm + mi * 16 + g + 8 * half;
                    int r = gr & 16383, bb = r >> 8, n = r & 255;
                    g_norms[t * 131072 + (h * 64 + bb) * 256 + n] = sqrtf(s);
                }
            }
        }
    }
}

// ---------------- 3) chunk stats: raw Gram (tf32 mma) + rank-1 correction ----------------
__global__ __launch_bounds__(256) void stats_kernel()
{
    extern __shared__ float sE[];        // [256][72]
    __shared__ float red[256];
    __shared__ float smu[64];
    __shared__ float r3[3][8];

    int tid = threadIdx.x;
    int bx = blockIdx.x;
    int t = bx >> 9;
    int rest = bx & 511;
    int c = rest >> 3, s = rest & 7;
    int h = c >> 3, b = ((c & 7) << 3) + s;
    const float* base = g_f + (size_t)t * FS + (size_t)(b * 256) * 512 + h * 64;

    for (int idx = tid; idx < 4096; idx += 256) {
        int n = idx >> 4, c4 = (idx & 15) * 4;
        *(float4*)&sE[n * 72 + c4] = *(const float4*)(base + (size_t)n * 512 + c4);
    }
    __syncthreads();

    {
        int i = tid & 63, grp = tid >> 6;
        float sm = 0.f;
        #pragma unroll 8
        for (int n = grp; n < 256; n += 4) sm += sE[n * 72 + i];
        red[tid] = sm;
        __syncthreads();
        if (tid < 64)
            smu[tid] = (red[tid] + red[tid + 64] + red[tid + 128] + red[tid + 192]) * (1.f / 256.f);
        __syncthreads();
    }

    int lane = tid & 31, wid = tid >> 5;
    int g = lane >> 2, t4 = lane & 3;
    int wm = (wid & 3) * 16, wn = (wid >> 2) * 32;
    float gacc[4][4] = {};
    #pragma unroll 4
    for (int ks = 0; ks < 32; ks++) {
        int kb8 = ks * 8;
        uint32_t af[4];
        af[0] = __float_as_uint(sE[(kb8 + t4) * 72 + wm + g]);
        af[1] = __float_as_uint(sE[(kb8 + t4) * 72 + wm + g + 8]);
        af[2] = __float_as_uint(sE[(kb8 + t4 + 4) * 72 + wm + g]);
        af[3] = __float_as_uint(sE[(kb8 + t4 + 4) * 72 + wm + g + 8]);
        #pragma unroll
        for (int ni = 0; ni < 4; ni++) {
            uint32_t b0 = __float_as_uint(sE[(kb8 + t4) * 72 + wn + ni * 8 + g]);
            uint32_t b1 = __float_as_uint(sE[(kb8 + t4 + 4) * 72 + wn + ni * 8 + g]);
            mma8(gacc[ni], af, b0, b1);
        }
    }

    int row0 = wm + g, row1 = wm + g + 8;
    float mr0 = smu[row0] * 256.f, mr1 = smu[row1] * 256.f;
    float tot = 0.f, dsum = 0.f, vsum = 0.f;
    #pragma unroll
    for (int ni = 0; ni < 4; ni++) {
        int c0 = wn + ni * 8 + 2 * t4, c1 = c0 + 1;
        float mc0 = smu[c0], mc1 = smu[c1];
        float g00 = gacc[ni][0] - mr0 * mc0;
        float g01 = gacc[ni][1] - mr0 * mc1;
        float g10 = gacc[ni][2] - mr1 * mc0;
        float g11 = gacc[ni][3] - mr1 * mc1;
        tot += g00 * g00 + g01 * g01 + g10 * g10 + g11 * g11;
        if (row0 == c0) { dsum += g00 * g00; vsum += fmaxf(0.f, 1.f - sqrtf(g00 * (1.f / 255.f) + 1e-8f)); }
        if (row0 == c1) { dsum += g01 * g01; vsum += fmaxf(0.f, 1.f - sqrtf(g01 * (1.f / 255.f) + 1e-8f)); }
        if (row1 == c0) { dsum += g10 * g10; vsum += fmaxf(0.f, 1.f - sqrtf(g10 * (1.f / 255.f) + 1e-8f)); }
        if (row1 == c1) { dsum += g11 * g11; vsum += fmaxf(0.f, 1.f - sqrtf(g11 * (1.f / 255.f) + 1e-8f)); }
    }

    float a0 = warp_sum(tot), a1 = warp_sum(dsum), a2 = warp_sum(vsum);
    if (!lane) { r3[0][wid] = a0; r3[1][wid] = a1; r3[2][wid] = a2; }
    __syncthreads();
    if (tid == 0) {
        float T = 0.f, D = 0.f, V = 0.f;
        #pragma unroll
        for (int i = 0; i < 8; i++) { T += r3[0][i]; D += r3[1][i]; V += r3[2][i]; }
        g_part[bx * 2 + 0] = V * (1.f / 512.f);
        g_part[bx * 2 + 1] = (T - D) * (1.f / (255.f * 255.f * 64.f * 8.f));
    }
}

// ---------------- 4) fused attention (unified grid) ----------------
__global__ __launch_bounds__(256) void attn_kernel(
    const float* __restrict__ cl, const float* __restrict__ vl)
{
    extern __shared__ float sh[];
    float* Qs  = sh;                       // [128][68]
    float* Ks  = sh + 128 * 68;            // [64][68]
    float* Vs  = sh + 128 * 68 + 64 * 68;  // [64][72]
    float* Ssm = Vs + 64 * 72;             // [128][68]

    int tid = threadIdx.x, lane = tid & 31, wid = tid >> 5;
    int g = lane >> 2, t4 = lane & 3;
    int wm = (wid >> 1) * 32, wn = (wid & 1) * 32;
    int nt = blockIdx.x, hb = blockIdx.y;
    int h = hb >> 6, b = hb & 63, c = hb >> 3;

    const float* qb = g_f + (size_t)(b * 256 + nt * 128) * 512 + h * 64;
    const float* kb = g_f + FS + (size_t)(b * 256) * 512 + h * 64;
    const float* vb = g_f + 2 * FS + (size_t)(b * 256) * 512 + h * 64;

    {
        int lrow = tid >> 4, lc4 = (tid & 15) * 4;
        #pragma unroll
        for (int l = 0; l < 8; l++) {
            int row = l * 16 + lrow;
            *(float4*)&Qs[row * 68 + lc4] = *(const float4*)(qb + (size_t)row * 512 + lc4);
        }
    }

    float cw = 1.f / (1.f + expf(-cl[0]));
    float vw = 1.f / (1.f + expf(-vl[0]));
    float cosw = 1.f - cw - vw;
    float Vq = 0.f, Cq = 0.f, Vk = 0.f, Ck = 0.f;
    #pragma unroll
    for (int s = 0; s < 8; s++) {
        Vq += g_part[(c * 8 + s) * 2];
        Cq += g_part[(c * 8 + s) * 2 + 1];
        Vk += g_part[(512 + c * 8 + s) * 2];
        Ck += g_part[(512 + c * 8 + s) * 2 + 1];
    }
    float biasv = cw * (Cq * Ck) + vw * (Vq * Vk);

    float qinv[2][2];
    #pragma unroll
    for (int mi = 0; mi < 2; mi++)
        #pragma unroll
        for (int half = 0; half < 2; half++) {
            int n = nt * 128 + wm + mi * 16 + g + 8 * half;
            qinv[mi][half] = cosw / g_norms[hb * 256 + n];
        }

    int krow = tid >> 2;
    int kc0 = (tid & 3) * 4;

    float oacc[2][4][4] = {};
    for (int mc = 0; mc < 4; mc++) {
        #pragma unroll
        for (int l = 0; l < 4; l++) {
            int col = kc0 + l * 16;
            *(float4*)&Ks[krow * 68 + col] =
                *(const float4*)(kb + (size_t)(mc * 64 + krow) * 512 + col);
            *(float4*)&Vs[krow * 72 + col] =
                *(const float4*)(vb + (size_t)(mc * 64 + krow) * 512 + col);
        }
        __syncthreads();

        float sacc[2][4][4] = {};
        #pragma unroll
        for (int ks = 0; ks < 8; ks++) {
            int kb8 = ks * 8;
            uint32_t af[2][4];
            #pragma unroll
            for (int mi = 0; mi < 2; mi++) {
                const float* ap = &Qs[(wm + mi * 16) * 68 + kb8];
                af[mi][0] = __float_as_uint(ap[g * 68 + t4]);
                af[mi][1] = __float_as_uint(ap[(g + 8) * 68 + t4]);
                af[mi][2] = __float_as_uint(ap[g * 68 + t4 + 4]);
                af[mi][3] = __float_as_uint(ap[(g + 8) * 68 + t4 + 4]);
            }
            #pragma unroll
            for (int ni = 0; ni < 4; ni++) {
                uint32_t b0 = __float_as_uint(Ks[(wn + ni * 8 + g) * 68 + kb8 + t4]);
                uint32_t b1 = __float_as_uint(Ks[(wn + ni * 8 + g) * 68 + kb8 + t4 + 4]);
                mma8(sacc[0][ni], af[0], b0, b1);
                mma8(sacc[1][ni], af[1], b0, b1);
            }
        }

        #pragma unroll
        for (int ni = 0; ni < 4; ni++) {
            int ml = wn + ni * 8 + 2 * t4;
            int m0 = mc * 64 + ml;
            float ki0 = 1.f / g_norms[131072 + hb * 256 + m0];
            float ki1 = 1.f / g_norms[131072 + hb * 256 + m0 + 1];
            #pragma unroll
            for (int mi = 0; mi < 2; mi++) {
                #pragma unroll
                for (int half = 0; half < 2; half++) {
                    int nl = wm + mi * 16 + g + 8 * half;
                    float2 o = make_float2(
                        tf32r(qinv[mi][half] * sacc[mi][ni][2 * half] * ki0 + biasv),
                        tf32r(qinv[mi][half] * sacc[mi][ni][2 * half + 1] * ki1 + biasv));
                    *(float2*)&Ssm[nl * 68 + ml] = o;
                }
            }
        }
        __syncthreads();

        #pragma unroll
        for (int ks = 0; ks < 8; ks++) {
            int kb8 = ks * 8;
            uint32_t af[2][4];
            #pragma unroll
            for (int mi = 0; mi < 2; mi++) {
                const float* ap = &Ssm[(wm + mi * 16) * 68 + kb8];
                af[mi][0] = __float_as_uint(ap[g * 68 + t4]);
                af[mi][1] = __float_as_uint(ap[(g + 8) * 68 + t4]);
                af[mi][2] = __float_as_uint(ap[g * 68 + t4 + 4]);
                af[mi][3] = __float_as_uint(ap[(g + 8) * 68 + t4 + 4]);
            }
            #pragma unroll
            for (int ni = 0; ni < 4; ni++) {
                uint32_t b0 = __float_as_uint(Vs[(kb8 + t4) * 72 + wn + ni * 8 + g]);
                uint32_t b1 = __float_as_uint(Vs[(kb8 + t4 + 4) * 72 + wn + ni * 8 + g]);
                mma8(oacc[0][ni], af[0], b0, b1);
                mma8(oacc[1][ni], af[1], b0, b1);
            }
        }
        __syncthreads();
    }

    #pragma unroll
    for (int mi = 0; mi < 2; mi++) {
        #pragma unroll
        for (int ni = 0; ni < 4; ni++) {
            int col = wn + ni * 8 + 2 * t4;
            int n0 = nt * 128 + wm + mi * 16 + g;
            *(float2*)(g_att + (size_t)(b * 256 + n0) * 512 + h * 64 + col) =
                make_float2(tf32r(oacc[mi][ni][0]), tf32r(oacc[mi][ni][1]));
            *(float2*)(g_att + (size_t)(b * 256 + n0 + 8) * 512 + h * 64 + col) =
                make_float2(tf32r(oacc[mi][ni][2]), tf32r(oacc[mi][ni][3]));
        }
    }
}

// ---------------- launch ----------------
extern "C" void kernel_launch(void* const* d_in, const int* in_sizes, int n_in,
                              void* d_out, int out_size)
{
    const float* q   = (const float*)d_in[0];
    const float* k   = (const float*)d_in[1];
    const float* v   = (const float*)d_in[2];
    const float* gma = (const float*)d_in[3];
    const float* bta = (const float*)d_in[4];
    const float* Win = (const float*)d_in[5];
    const float* Wout= (const float*)d_in[6];
    const float* bout= (const float*)d_in[7];
    const float* covl= (const float*)d_in[8];
    const float* varl= (const float*)d_in[9];
    float* out = (float*)d_out;

    void *pxn, *pf, *patt, *pwin, *pwout;
    cudaGetSymbolAddress(&pxn, g_xn);
    cudaGetSymbolAddress(&pf, g_f);
    cudaGetSymbolAddress(&patt, g_att);
    cudaGetSymbolAddress(&pwin, g_win);
    cudaGetSymbolAddress(&pwout, g_wout);

    constexpr int ATTN_SMEM  = (128 * 68 + 64 * 68 + 64 * 72 + 128 * 68) * 4;
    constexpr int STATS_SMEM = 256 * 72 * 4;

    static cudaStream_t s2;
    static cudaEvent_t evRoot, evW, evV, evQK, evS;
    static bool init_done = false;
    if (!init_done) {
        cudaFuncSetAttribute(attn_kernel,  cudaFuncAttributeMaxDynamicSharedMemorySize, ATTN_SMEM);
        cudaFuncSetAttribute(stats_kernel, cudaFuncAttributeMaxDynamicSharedMemorySize, STATS_SMEM);
        cudaStreamCreateWithFlags(&s2, cudaStreamNonBlocking);
        cudaEventCreateWithFlags(&evRoot, cudaEventDisableTiming);
        cudaEventCreateWithFlags(&evW, cudaEventDisableTiming);
        cudaEventCreateWithFlags(&evV, cudaEventDisableTiming);
        cudaEventCreateWithFlags(&evQK, cudaEventDisableTiming);
        cudaEventCreateWithFlags(&evS, cudaEventDisableTiming);
        init_done = true;
    }

    // fork s2 from the capturing stream
    cudaEventRecord(evRoot, 0);
    cudaStreamWaitEvent(s2, evRoot, 0);

    // s2: wround, then ln for v rows
    wround_kernel<<<256, 256, 0, s2>>>(Win, Wout);
    cudaEventRecord(evW, s2);
    ln_kernel<<<2048, 256, 0, s2>>>(q, k, v, gma, bta, 4096);   // v rows
    cudaEventRecord(evV, s2);

    // main: ln for q,k rows
    ln_kernel<<<4096, 256>>>(q, k, v, gma, bta, 0);
    cudaStreamWaitEvent(0, evW, 0);

    // proj q,k rows
    mm_kernel<true><<<dim3(4, 256), 128>>>((const float*)pxn, (const float*)pwin,
                                           (float*)pf, nullptr, 0);
    cudaEventRecord(evQK, 0);

    // stats on s2, concurrent with proj_v
    cudaStreamWaitEvent(s2, evQK, 0);
    stats_kernel<<<1024, 256, STATS_SMEM, s2>>>();
    cudaEventRecord(evS, s2);

    // proj v rows on main (needs ln_v done)
    cudaStreamWaitEvent(0, evV, 0);
    mm_kernel<true><<<dim3(4, 128), 128>>>((const float*)pxn, (const float*)pwin,
                                           (float*)pf, nullptr, 256);

    // join stats, then unified attention
    cudaStreamWaitEvent(0, evS, 0);
    attn_kernel<<<dim3(2, 512), 256, ATTN_SMEM>>>(covl, varl);

    // output GEMM
    mm_kernel<false><<<dim3(4, 128), 128>>>((const float*)patt, (const float*)pwout,
                                            out, bout, 0);
}

// round 14
// speedup vs baseline: 1.1592x; 1.0300x over previous
#include <cuda_runtime.h>
#include <math.h>
#include <stdint.h>

constexpr size_t FS = (size_t)16384 * 512;

__device__ float g_xn[3 * FS];                      // LN output (tf32-rounded)
__device__ float g_f[3 * FS];                       // projected features (tf32-rounded)
__device__ float g_att[FS];                         // attention out (tf32-rounded)
__device__ float g_win[512 * 512];
__device__ float g_wout[512 * 512];
__device__ float g_norms[2 * 512 * 256];            // qn,kn [t][hb][n]
__device__ float g_part[2048];                      // stats partials [t][c][s][2]

__device__ __forceinline__ float warp_sum(float v) {
    #pragma unroll
    for (int o = 16; o; o >>= 1) v += __shfl_xor_sync(0xffffffffu, v, o);
    return v;
}
__device__ __forceinline__ float tf32r(float x) {
    uint32_t u;
    asm("cvt.rna.tf32.f32 %0, %1;" : "=r"(u) : "f"(x));
    return __uint_as_float(u);
}
__device__ __forceinline__ void mma8(float c[4], const uint32_t a[4], uint32_t b0, uint32_t b1) {
    asm volatile(
        "mma.sync.aligned.m16n8k8.row.col.f32.tf32.tf32.f32 "
        "{%0,%1,%2,%3},{%4,%5,%6,%7},{%8,%9},{%0,%1,%2,%3};"
        : "+f"(c[0]), "+f"(c[1]), "+f"(c[2]), "+f"(c[3])
        : "r"(a[0]), "r"(a[1]), "r"(a[2]), "r"(a[3]), "r"(b0), "r"(b1));
}
__device__ __forceinline__ void cp16(uint32_t saddr, const void* gptr) {
    asm volatile("cp.async.cg.shared.global [%0], [%1], 16;" :: "r"(saddr), "l"(gptr));
}
__device__ __forceinline__ void cp_commit() {
    asm volatile("cp.async.commit_group;");
}
__device__ __forceinline__ void cp_wait1() {
    asm volatile("cp.async.wait_group 1;");
}
__device__ __forceinline__ void cp_wait0() {
    asm volatile("cp.async.wait_group 0;");
}

// ---------------- 0) round weights once ----------------
__global__ __launch_bounds__(256) void wround_kernel(
    const float* __restrict__ Win, const float* __restrict__ Wout)
{
    int idx = (blockIdx.x * 256 + threadIdx.x) * 4;
    float4 a = *(const float4*)(Win + idx);
    a.x = tf32r(a.x); a.y = tf32r(a.y); a.z = tf32r(a.z); a.w = tf32r(a.w);
    *(float4*)(g_win + idx) = a;
    float4 b = *(const float4*)(Wout + idx);
    b.x = tf32r(b.x); b.y = tf32r(b.y); b.z = tf32r(b.z); b.w = tf32r(b.w);
    *(float4*)(g_wout + idx) = b;
}

// ---------------- 1) LayerNorm, writes tf32-rounded output (+ block offset) ----------------
__global__ __launch_bounds__(256) void ln_kernel(
    const float* __restrict__ q, const float* __restrict__ k, const float* __restrict__ v,
    const float* __restrict__ gma, const float* __restrict__ bta, int blockoff)
{
    int warp = threadIdx.x >> 5, lane = threadIdx.x & 31;
    int row = (blockIdx.x + blockoff) * 8 + warp;
    int t = row >> 14, r = row & 16383;
    const float* src = (t == 0 ? q : (t == 1 ? k : v)) + (size_t)r * 512;
    float x[16], s = 0.f;
    #pragma unroll
    for (int i = 0; i < 16; i++) { x[i] = src[lane + 32 * i]; s += x[i]; }
    s = warp_sum(s);
    float mu = s * (1.f / 512.f), ss = 0.f;
    #pragma unroll
    for (int i = 0; i < 16; i++) { float d = x[i] - mu; ss += d * d; }
    ss = warp_sum(ss);
    float rs = rsqrtf(ss * (1.f / 512.f) + 1e-5f);
    float* dst = g_xn + (size_t)row * 512;
    #pragma unroll
    for (int i = 0; i < 16; i++) {
        int c = lane + 32 * i;
        dst[c] = tf32r((x[i] - mu) * rs * gma[c] + bta[c]);
    }
}

// ---------------- 2/6) tf32 GEMM 128x128, 4 warps of 64x64, cp.async 3-stage ----------------
template<bool PROJ>
__global__ __launch_bounds__(128, 3) void mm_kernel(
    const float* __restrict__ A, const float* __restrict__ B,
    float* __restrict__ C, const float* __restrict__ bias, int rowoff)
{
    __shared__ float As[3][128 * 20];
    __shared__ float Bs[3][16 * 136];

    int tid = threadIdx.x, lane = tid & 31, wid = tid >> 5;   // wid 0..3
    int g = lane >> 2, t4 = lane & 3;
    int wm = (wid >> 1) * 64, wn = (wid & 1) * 64;            // warp tile 64x64
    int bx = blockIdx.x;
    int grow = (blockIdx.y + rowoff) * 128;

    int arow = tid >> 2, ac4 = (tid & 3) * 4;                 // arow 0..31
    const float* srcA[4];
    #pragma unroll
    for (int l = 0; l < 4; l++)
        srcA[l] = A + (size_t)(grow + l * 32 + arow) * 512;
    int brow = tid >> 5, bcol = (tid & 31) * 4;               // brow 0..3
    const float* Bbase = B + (size_t)bx * 128 + bcol;

    uint32_t sAbase = (uint32_t)__cvta_generic_to_shared(&As[0][0]);
    uint32_t sBbase = (uint32_t)__cvta_generic_to_shared(&Bs[0][0]);
    constexpr uint32_t ASTG = 128 * 20 * 4;
    constexpr uint32_t BSTG = 16 * 136 * 4;

    float acc[4][8][4] = {};

    // prologue: stages 0,1
    #pragma unroll
    for (int st = 0; st < 2; st++) {
        int bk = st * 16;
        #pragma unroll
        for (int l = 0; l < 4; l++) {
            cp16(sAbase + st * ASTG + ((l * 32 + arow) * 20 + ac4) * 4, srcA[l] + bk + ac4);
            cp16(sBbase + st * BSTG + ((l * 4 + brow) * 136 + bcol) * 4,
                 Bbase + (size_t)(bk + l * 4 + brow) * 512);
        }
        cp_commit();
    }

    for (int t = 0; t < 32; t++) {
        if (t == 31) cp_wait0(); else cp_wait1();
        __syncthreads();

        if (t + 2 < 32) {
            int st = (t + 2) % 3;
            int bk = (t + 2) * 16;
            #pragma unroll
            for (int l = 0; l < 4; l++) {
                cp16(sAbase + st * ASTG + ((l * 32 + arow) * 20 + ac4) * 4, srcA[l] + bk + ac4);
                cp16(sBbase + st * BSTG + ((l * 4 + brow) * 136 + bcol) * 4,
                     Bbase + (size_t)(bk + l * 4 + brow) * 512);
            }
            cp_commit();
        }

        const float* Ab = As[t % 3];
        const float* Bb = Bs[t % 3];
        #pragma unroll
        for (int ks = 0; ks < 2; ks++) {
            int kb = ks * 8;
            uint32_t af[4][4];
            #pragma unroll
            for (int mi = 0; mi < 4; mi++) {
                const float* ap = &Ab[(wm + mi * 16) * 20 + kb];
                af[mi][0] = __float_as_uint(ap[g * 20 + t4]);
                af[mi][1] = __float_as_uint(ap[(g + 8) * 20 + t4]);
                af[mi][2] = __float_as_uint(ap[g * 20 + t4 + 4]);
                af[mi][3] = __float_as_uint(ap[(g + 8) * 20 + t4 + 4]);
            }
            #pragma unroll
            for (int ni = 0; ni < 8; ni++) {
                uint32_t b0 = __float_as_uint(Bb[(kb + t4) * 136 + wn + ni * 8 + g]);
                uint32_t b1 = __float_as_uint(Bb[(kb + t4 + 4) * 136 + wn + ni * 8 + g]);
                #pragma unroll
                for (int mi = 0; mi < 4; mi++)
                    mma8(acc[mi][ni], af[mi], b0, b1);
            }
        }
        __syncthreads();
    }

    if (PROJ) {
        #pragma unroll
        for (int mi = 0; mi < 4; mi++)
            #pragma unroll
            for (int ni = 0; ni < 8; ni++)
                #pragma unroll
                for (int p = 0; p < 4; p++)
                    acc[mi][ni][p] = tf32r(acc[mi][ni][p]);
    }

    #pragma unroll
    for (int mi = 0; mi < 4; mi++) {
        #pragma unroll
        for (int ni = 0; ni < 8; ni++) {
            int col = bx * 128 + wn + ni * 8 + 2 * t4;
            float2 o0 = make_float2(acc[mi][ni][0], acc[mi][ni][1]);
            float2 o1 = make_float2(acc[mi][ni][2], acc[mi][ni][3]);
            if (!PROJ) {
                float2 bb = *(const float2*)(bias + col);
                o0.x += bb.x; o0.y += bb.y; o1.x += bb.x; o1.y += bb.y;
            }
            int r0 = grow + wm + mi * 16 + g;
            *(float2*)(C + (size_t)r0 * 512 + col) = o0;
            *(float2*)(C + (size_t)(r0 + 8) * 512 + col) = o1;
        }
    }

    if (PROJ && (grow >> 14) < 2) {
        int t = grow >> 14;
        int h = bx * 2 + (wid & 1);
        #pragma unroll
        for (int mi = 0; mi < 4; mi++) {
            #pragma unroll
            for (int half = 0; half < 2; half++) {
                float s = 0.f;
                #pragma unroll
                for (int ni = 0; ni < 8; ni++) {
                    float x = acc[mi][ni][2 * half], y = acc[mi][ni][2 * half + 1];
                    s += x * x + y * y;
                }
                s += __shfl_xor_sync(0xffffffffu, s, 1);
                s += __shfl_xor_sync(0xffffffffu, s, 2);
                if (t4 == 0) {
                    int gr = grow + wm + mi * 16 + g + 8 * half;
                    int r = gr & 16383, bb = r >> 8, n = r & 255;
                    g_norms[t * 131072 + (h * 64 + bb) * 256 + n] = sqrtf(s);
                }
            }
        }
    }
}

// ---------------- 3) chunk stats: raw Gram (tf32 mma) + rank-1 correction ----------------
__global__ __launch_bounds__(256) void stats_kernel()
{
    extern __shared__ float sE[];        // [256][72]
    __shared__ float red[256];
    __shared__ float smu[64];
    __shared__ float r3[3][8];

    int tid = threadIdx.x;
    int bx = blockIdx.x;
    int t = bx >> 9;
    int rest = bx & 511;
    int c = rest >> 3, s = rest & 7;
    int h = c >> 3, b = ((c & 7) << 3) + s;
    const float* base = g_f + (size_t)t * FS + (size_t)(b * 256) * 512 + h * 64;

    for (int idx = tid; idx < 4096; idx += 256) {
        int n = idx >> 4, c4 = (idx & 15) * 4;
        *(float4*)&sE[n * 72 + c4] = *(const float4*)(base + (size_t)n * 512 + c4);
    }
    __syncthreads();

    {
        int i = tid & 63, grp = tid >> 6;
        float sm = 0.f;
        #pragma unroll 8
        for (int n = grp; n < 256; n += 4) sm += sE[n * 72 + i];
        red[tid] = sm;
        __syncthreads();
        if (tid < 64)
            smu[tid] = (red[tid] + red[tid + 64] + red[tid + 128] + red[tid + 192]) * (1.f / 256.f);
        __syncthreads();
    }

    int lane = tid & 31, wid = tid >> 5;
    int g = lane >> 2, t4 = lane & 3;
    int wm = (wid & 3) * 16, wn = (wid >> 2) * 32;
    float gacc[4][4] = {};
    #pragma unroll 4
    for (int ks = 0; ks < 32; ks++) {
        int kb8 = ks * 8;
        uint32_t af[4];
        af[0] = __float_as_uint(sE[(kb8 + t4) * 72 + wm + g]);
        af[1] = __float_as_uint(sE[(kb8 + t4) * 72 + wm + g + 8]);
        af[2] = __float_as_uint(sE[(kb8 + t4 + 4) * 72 + wm + g]);
        af[3] = __float_as_uint(sE[(kb8 + t4 + 4) * 72 + wm + g + 8]);
        #pragma unroll
        for (int ni = 0; ni < 4; ni++) {
            uint32_t b0 = __float_as_uint(sE[(kb8 + t4) * 72 + wn + ni * 8 + g]);
            uint32_t b1 = __float_as_uint(sE[(kb8 + t4 + 4) * 72 + wn + ni * 8 + g]);
            mma8(gacc[ni], af, b0, b1);
        }
    }

    int row0 = wm + g, row1 = wm + g + 8;
    float mr0 = smu[row0] * 256.f, mr1 = smu[row1] * 256.f;
    float tot = 0.f, dsum = 0.f, vsum = 0.f;
    #pragma unroll
    for (int ni = 0; ni < 4; ni++) {
        int c0 = wn + ni * 8 + 2 * t4, c1 = c0 + 1;
        float mc0 = smu[c0], mc1 = smu[c1];
        float g00 = gacc[ni][0] - mr0 * mc0;
        float g01 = gacc[ni][1] - mr0 * mc1;
        float g10 = gacc[ni][2] - mr1 * mc0;
        float g11 = gacc[ni][3] - mr1 * mc1;
        tot += g00 * g00 + g01 * g01 + g10 * g10 + g11 * g11;
        if (row0 == c0) { dsum += g00 * g00; vsum += fmaxf(0.f, 1.f - sqrtf(g00 * (1.f / 255.f) + 1e-8f)); }
        if (row0 == c1) { dsum += g01 * g01; vsum += fmaxf(0.f, 1.f - sqrtf(g01 * (1.f / 255.f) + 1e-8f)); }
        if (row1 == c0) { dsum += g10 * g10; vsum += fmaxf(0.f, 1.f - sqrtf(g10 * (1.f / 255.f) + 1e-8f)); }
        if (row1 == c1) { dsum += g11 * g11; vsum += fmaxf(0.f, 1.f - sqrtf(g11 * (1.f / 255.f) + 1e-8f)); }
    }

    float a0 = warp_sum(tot), a1 = warp_sum(dsum), a2 = warp_sum(vsum);
    if (!lane) { r3[0][wid] = a0; r3[1][wid] = a1; r3[2][wid] = a2; }
    __syncthreads();
    if (tid == 0) {
        float T = 0.f, D = 0.f, V = 0.f;
        #pragma unroll
        for (int i = 0; i < 8; i++) { T += r3[0][i]; D += r3[1][i]; V += r3[2][i]; }
        g_part[bx * 2 + 0] = V * (1.f / 512.f);
        g_part[bx * 2 + 1] = (T - D) * (1.f / (255.f * 255.f * 64.f * 8.f));
    }
}

// ---------------- 4) fused attention (unified grid) ----------------
__global__ __launch_bounds__(256) void attn_kernel(
    const float* __restrict__ cl, const float* __restrict__ vl)
{
    extern __shared__ float sh[];
    float* Qs  = sh;                       // [128][68]
    float* Ks  = sh + 128 * 68;            // [64][68]
    float* Vs  = sh + 128 * 68 + 64 * 68;  // [64][72]
    float* Ssm = Vs + 64 * 72;             // [128][68]

    int tid = threadIdx.x, lane = tid & 31, wid = tid >> 5;
    int g = lane >> 2, t4 = lane & 3;
    int wm = (wid >> 1) * 32, wn = (wid & 1) * 32;
    int nt = blockIdx.x, hb = blockIdx.y;
    int h = hb >> 6, b = hb & 63, c = hb >> 3;

    const float* qb = g_f + (size_t)(b * 256 + nt * 128) * 512 + h * 64;
    const float* kb = g_f + FS + (size_t)(b * 256) * 512 + h * 64;
    const float* vb = g_f + 2 * FS + (size_t)(b * 256) * 512 + h * 64;

    {
        int lrow = tid >> 4, lc4 = (tid & 15) * 4;
        #pragma unroll
        for (int l = 0; l < 8; l++) {
            int row = l * 16 + lrow;
            *(float4*)&Qs[row * 68 + lc4] = *(const float4*)(qb + (size_t)row * 512 + lc4);
        }
    }

    float cw = 1.f / (1.f + expf(-cl[0]));
    float vw = 1.f / (1.f + expf(-vl[0]));
    float cosw = 1.f - cw - vw;
    float Vq = 0.f, Cq = 0.f, Vk = 0.f, Ck = 0.f;
    #pragma unroll
    for (int s = 0; s < 8; s++) {
        Vq += g_part[(c * 8 + s) * 2];
        Cq += g_part[(c * 8 + s) * 2 + 1];
        Vk += g_part[(512 + c * 8 + s) * 2];
        Ck += g_part[(512 + c * 8 + s) * 2 + 1];
    }
    float biasv = cw * (Cq * Ck) + vw * (Vq * Vk);

    float qinv[2][2];
    #pragma unroll
    for (int mi = 0; mi < 2; mi++)
        #pragma unroll
        for (int half = 0; half < 2; half++) {
            int n = nt * 128 + wm + mi * 16 + g + 8 * half;
            qinv[mi][half] = cosw / g_norms[hb * 256 + n];
        }

    int krow = tid >> 2;
    int kc0 = (tid & 3) * 4;

    float oacc[2][4][4] = {};
    for (int mc = 0; mc < 4; mc++) {
        #pragma unroll
        for (int l = 0; l < 4; l++) {
            int col = kc0 + l * 16;
            *(float4*)&Ks[krow * 68 + col] =
                *(const float4*)(kb + (size_t)(mc * 64 + krow) * 512 + col);
            *(float4*)&Vs[krow * 72 + col] =
                *(const float4*)(vb + (size_t)(mc * 64 + krow) * 512 + col);
        }
        __syncthreads();

        float sacc[2][4][4] = {};
        #pragma unroll
        for (int ks = 0; ks < 8; ks++) {
            int kb8 = ks * 8;
            uint32_t af[2][4];
            #pragma unroll
            for (int mi = 0; mi < 2; mi++) {
                const float* ap = &Qs[(wm + mi * 16) * 68 + kb8];
                af[mi][0] = __float_as_uint(ap[g * 68 + t4]);
                af[mi][1] = __float_as_uint(ap[(g + 8) * 68 + t4]);
                af[mi][2] = __float_as_uint(ap[g * 68 + t4 + 4]);
                af[mi][3] = __float_as_uint(ap[(g + 8) * 68 + t4 + 4]);
            }
            #pragma unroll
            for (int ni = 0; ni < 4; ni++) {
                uint32_t b0 = __float_as_uint(Ks[(wn + ni * 8 + g) * 68 + kb8 + t4]);
                uint32_t b1 = __float_as_uint(Ks[(wn + ni * 8 + g) * 68 + kb8 + t4 + 4]);
                mma8(sacc[0][ni], af[0], b0, b1);
                mma8(sacc[1][ni], af[1], b0, b1);
            }
        }

        #pragma unroll
        for (int ni = 0; ni < 4; ni++) {
            int ml = wn + ni * 8 + 2 * t4;
            int m0 = mc * 64 + ml;
            float ki0 = 1.f / g_norms[131072 + hb * 256 + m0];
            float ki1 = 1.f / g_norms[131072 + hb * 256 + m0 + 1];
            #pragma unroll
            for (int mi = 0; mi < 2; mi++) {
                #pragma unroll
                for (int half = 0; half < 2; half++) {
                    int nl = wm + mi * 16 + g + 8 * half;
                    float2 o = make_float2(
                        tf32r(qinv[mi][half] * sacc[mi][ni][2 * half] * ki0 + biasv),
                        tf32r(qinv[mi][half] * sacc[mi][ni][2 * half + 1] * ki1 + biasv));
                    *(float2*)&Ssm[nl * 68 + ml] = o;
                }
            }
        }
        __syncthreads();

        #pragma unroll
        for (int ks = 0; ks < 8; ks++) {
            int kb8 = ks * 8;
            uint32_t af[2][4];
            #pragma unroll
            for (int mi = 0; mi < 2; mi++) {
                const float* ap = &Ssm[(wm + mi * 16) * 68 + kb8];
                af[mi][0] = __float_as_uint(ap[g * 68 + t4]);
                af[mi][1] = __float_as_uint(ap[(g + 8) * 68 + t4]);
                af[mi][2] = __float_as_uint(ap[g * 68 + t4 + 4]);
                af[mi][3] = __float_as_uint(ap[(g + 8) * 68 + t4 + 4]);
            }
            #pragma unroll
            for (int ni = 0; ni < 4; ni++) {
                uint32_t b0 = __float_as_uint(Vs[(kb8 + t4) * 72 + wn + ni * 8 + g]);
                uint32_t b1 = __float_as_uint(Vs[(kb8 + t4 + 4) * 72 + wn + ni * 8 + g]);
                mma8(oacc[0][ni], af[0], b0, b1);
                mma8(oacc[1][ni], af[1], b0, b1);
            }
        }
        __syncthreads();
    }

    #pragma unroll
    for (int mi = 0; mi < 2; mi++) {
        #pragma unroll
        for (int ni = 0; ni < 4; ni++) {
            int col = wn + ni * 8 + 2 * t4;
            int n0 = nt * 128 + wm + mi * 16 + g;
            *(float2*)(g_att + (size_t)(b * 256 + n0) * 512 + h * 64 + col) =
                make_float2(tf32r(oacc[mi][ni][0]), tf32r(oacc[mi][ni][1]));
            *(float2*)(g_att + (size_t)(b * 256 + n0 + 8) * 512 + h * 64 + col) =
                make_float2(tf32r(oacc[mi][ni][2]), tf32r(oacc[mi][ni][3]));
        }
    }
}

// ---------------- launch ----------------
extern "C" void kernel_launch(void* const* d_in, const int* in_sizes, int n_in,
                              void* d_out, int out_size)
{
    const float* q   = (const float*)d_in[0];
    const float* k   = (const float*)d_in[1];
    const float* v   = (const float*)d_in[2];
    const float* gma = (const float*)d_in[3];
    const float* bta = (const float*)d_in[4];
    const float* Win = (const float*)d_in[5];
    const float* Wout= (const float*)d_in[6];
    const float* bout= (const float*)d_in[7];
    const float* covl= (const float*)d_in[8];
    const float* varl= (const float*)d_in[9];
    float* out = (float*)d_out;

    void *pxn, *pf, *patt, *pwin, *pwout;
    cudaGetSymbolAddress(&pxn, g_xn);
    cudaGetSymbolAddress(&pf, g_f);
    cudaGetSymbolAddress(&patt, g_att);
    cudaGetSymbolAddress(&pwin, g_win);
    cudaGetSymbolAddress(&pwout, g_wout);

    constexpr int ATTN_SMEM  = (128 * 68 + 64 * 68 + 64 * 72 + 128 * 68) * 4;
    constexpr int STATS_SMEM = 256 * 72 * 4;

    static cudaStream_t s2;
    static cudaEvent_t evRoot, evW, evV, evQK, evS;
    static bool init_done = false;
    if (!init_done) {
        cudaFuncSetAttribute(attn_kernel,  cudaFuncAttributeMaxDynamicSharedMemorySize, ATTN_SMEM);
        cudaFuncSetAttribute(stats_kernel, cudaFuncAttributeMaxDynamicSharedMemorySize, STATS_SMEM);
        cudaStreamCreateWithFlags(&s2, cudaStreamNonBlocking);
        cudaEventCreateWithFlags(&evRoot, cudaEventDisableTiming);
        cudaEventCreateWithFlags(&evW, cudaEventDisableTiming);
        cudaEventCreateWithFlags(&evV, cudaEventDisableTiming);
        cudaEventCreateWithFlags(&evQK, cudaEventDisableTiming);
        cudaEventCreateWithFlags(&evS, cudaEventDisableTiming);
        init_done = true;
    }

    // fork s2 from the capturing stream
    cudaEventRecord(evRoot, 0);
    cudaStreamWaitEvent(s2, evRoot, 0);

    // s2: wround, then ln for v rows
    wround_kernel<<<256, 256, 0, s2>>>(Win, Wout);
    cudaEventRecord(evW, s2);
    ln_kernel<<<2048, 256, 0, s2>>>(q, k, v, gma, bta, 4096);   // v rows
    cudaEventRecord(evV, s2);

    // main: ln for q,k rows
    ln_kernel<<<4096, 256>>>(q, k, v, gma, bta, 0);
    cudaStreamWaitEvent(0, evW, 0);

    // proj q,k rows
    mm_kernel<true><<<dim3(4, 256), 128>>>((const float*)pxn, (const float*)pwin,
                                           (float*)pf, nullptr, 0);
    cudaEventRecord(evQK, 0);

    // stats on s2, concurrent with proj_v
    cudaStreamWaitEvent(s2, evQK, 0);
    stats_kernel<<<1024, 256, STATS_SMEM, s2>>>();
    cudaEventRecord(evS, s2);

    // proj v rows on main (needs ln_v done)
    cudaStreamWaitEvent(0, evV, 0);
    mm_kernel<true><<<dim3(4, 128), 128>>>((const float*)pxn, (const float*)pwin,
                                           (float*)pf, nullptr, 256);

    // join stats, then unified attention
    cudaStreamWaitEvent(0, evS, 0);
    attn_kernel<<<dim3(2, 512), 256, ATTN_SMEM>>>(covl, varl);

    // output GEMM
    mm_kernel<false><<<dim3(4, 128), 128>>>((const float*)patt, (const float*)pwout,
                                            out, bout, 0);
}

// round 15
// speedup vs baseline: 1.1699x; 1.0093x over previous
#include <cuda_runtime.h>
#include <math.h>
#include <stdint.h>

constexpr size_t FS = (size_t)16384 * 512;

__device__ float g_xn[3 * FS];                      // LN output (tf32-rounded)
__device__ float g_f[3 * FS];                       // projected features (tf32-rounded)
__device__ float g_att[FS];                         // attention out (tf32-rounded)
__device__ float g_win[512 * 512];
__device__ float g_wout[512 * 512];
__device__ float g_norms[2 * 512 * 256];            // qn,kn [t][hb][n]
__device__ float g_part[2048];                      // stats partials [t][c][s][2]

__device__ __forceinline__ float warp_sum(float v) {
    #pragma unroll
    for (int o = 16; o; o >>= 1) v += __shfl_xor_sync(0xffffffffu, v, o);
    return v;
}
__device__ __forceinline__ float tf32r(float x) {
    uint32_t u;
    asm("cvt.rna.tf32.f32 %0, %1;" : "=r"(u) : "f"(x));
    return __uint_as_float(u);
}
__device__ __forceinline__ void mma8(float c[4], const uint32_t a[4], uint32_t b0, uint32_t b1) {
    asm volatile(
        "mma.sync.aligned.m16n8k8.row.col.f32.tf32.tf32.f32 "
        "{%0,%1,%2,%3},{%4,%5,%6,%7},{%8,%9},{%0,%1,%2,%3};"
        : "+f"(c[0]), "+f"(c[1]), "+f"(c[2]), "+f"(c[3])
        : "r"(a[0]), "r"(a[1]), "r"(a[2]), "r"(a[3]), "r"(b0), "r"(b1));
}
__device__ __forceinline__ void cp16(uint32_t saddr, const void* gptr) {
    asm volatile("cp.async.cg.shared.global [%0], [%1], 16;" :: "r"(saddr), "l"(gptr));
}
__device__ __forceinline__ void cp_commit() {
    asm volatile("cp.async.commit_group;");
}
__device__ __forceinline__ void cp_wait1() {
    asm volatile("cp.async.wait_group 1;");
}
__device__ __forceinline__ void cp_wait0() {
    asm volatile("cp.async.wait_group 0;");
}

// ---------------- 0) round weights once ----------------
__global__ __launch_bounds__(256) void wround_kernel(
    const float* __restrict__ Win, const float* __restrict__ Wout)
{
    int idx = (blockIdx.x * 256 + threadIdx.x) * 4;
    float4 a = *(const float4*)(Win + idx);
    a.x = tf32r(a.x); a.y = tf32r(a.y); a.z = tf32r(a.z); a.w = tf32r(a.w);
    *(float4*)(g_win + idx) = a;
    float4 b = *(const float4*)(Wout + idx);
    b.x = tf32r(b.x); b.y = tf32r(b.y); b.z = tf32r(b.z); b.w = tf32r(b.w);
    *(float4*)(g_wout + idx) = b;
}

// ---------------- 1) LayerNorm, writes tf32-rounded output (+ block offset) ----------------
__global__ __launch_bounds__(256) void ln_kernel(
    const float* __restrict__ q, const float* __restrict__ k, const float* __restrict__ v,
    const float* __restrict__ gma, const float* __restrict__ bta, int blockoff)
{
    int warp = threadIdx.x >> 5, lane = threadIdx.x & 31;
    int row = (blockIdx.x + blockoff) * 8 + warp;
    int t = row >> 14, r = row & 16383;
    const float* src = (t == 0 ? q : (t == 1 ? k : v)) + (size_t)r * 512;
    float x[16], s = 0.f;
    #pragma unroll
    for (int i = 0; i < 16; i++) { x[i] = src[lane + 32 * i]; s += x[i]; }
    s = warp_sum(s);
    float mu = s * (1.f / 512.f), ss = 0.f;
    #pragma unroll
    for (int i = 0; i < 16; i++) { float d = x[i] - mu; ss += d * d; }
    ss = warp_sum(ss);
    float rs = rsqrtf(ss * (1.f / 512.f) + 1e-5f);
    float* dst = g_xn + (size_t)row * 512;
    #pragma unroll
    for (int i = 0; i < 16; i++) {
        int c = lane + 32 * i;
        dst[c] = tf32r((x[i] - mu) * rs * gma[c] + bta[c]);
    }
}

// ---- 2/6) tf32 GEMM 128x128, 8 warps of 32x64, cp.async 3-stage, 1 sync/iter ----
template<bool PROJ>
__global__ __launch_bounds__(256, 2) void mm_kernel(
    const float* __restrict__ A, const float* __restrict__ B,
    float* __restrict__ C, const float* __restrict__ bias, int rowoff)
{
    __shared__ float As[3][128 * 20];
    __shared__ float Bs[3][16 * 136];

    int tid = threadIdx.x, lane = tid & 31, wid = tid >> 5;   // wid 0..7
    int g = lane >> 2, t4 = lane & 3;
    int wm = (wid >> 1) * 32, wn = (wid & 1) * 64;            // warp tile 32x64
    int bx = blockIdx.x;
    int grow = (blockIdx.y + rowoff) * 128;

    int arow = tid >> 2, ac4 = (tid & 3) * 4;                 // arow 0..63
    const float* srcA[2];
    #pragma unroll
    for (int l = 0; l < 2; l++)
        srcA[l] = A + (size_t)(grow + l * 64 + arow) * 512;
    int brow = tid >> 5, bcol = (tid & 31) * 4;               // brow 0..7
    const float* Bbase = B + (size_t)bx * 128 + bcol;

    uint32_t sAbase = (uint32_t)__cvta_generic_to_shared(&As[0][0]);
    uint32_t sBbase = (uint32_t)__cvta_generic_to_shared(&Bs[0][0]);
    constexpr uint32_t ASTG = 128 * 20 * 4;
    constexpr uint32_t BSTG = 16 * 136 * 4;

    float acc[2][8][4] = {};

    // prologue: stages 0,1
    #pragma unroll
    for (int st = 0; st < 2; st++) {
        int bk = st * 16;
        #pragma unroll
        for (int l = 0; l < 2; l++) {
            cp16(sAbase + st * ASTG + ((l * 64 + arow) * 20 + ac4) * 4, srcA[l] + bk + ac4);
            cp16(sBbase + st * BSTG + ((l * 8 + brow) * 136 + bcol) * 4,
                 Bbase + (size_t)(bk + l * 8 + brow) * 512);
        }
        cp_commit();
    }

    for (int t = 0; t < 32; t++) {
        if (t == 31) cp_wait0(); else cp_wait1();
        __syncthreads();

        if (t + 2 < 32) {
            int st = (t + 2) % 3;
            int bk = (t + 2) * 16;
            #pragma unroll
            for (int l = 0; l < 2; l++) {
                cp16(sAbase + st * ASTG + ((l * 64 + arow) * 20 + ac4) * 4, srcA[l] + bk + ac4);
                cp16(sBbase + st * BSTG + ((l * 8 + brow) * 136 + bcol) * 4,
                     Bbase + (size_t)(bk + l * 8 + brow) * 512);
            }
            cp_commit();
        }

        const float* Ab = As[t % 3];
        const float* Bb = Bs[t % 3];
        #pragma unroll
        for (int ks = 0; ks < 2; ks++) {
            int kb = ks * 8;
            uint32_t af[2][4];
            #pragma unroll
            for (int mi = 0; mi < 2; mi++) {
                const float* ap = &Ab[(wm + mi * 16) * 20 + kb];
                af[mi][0] = __float_as_uint(ap[g * 20 + t4]);
                af[mi][1] = __float_as_uint(ap[(g + 8) * 20 + t4]);
                af[mi][2] = __float_as_uint(ap[g * 20 + t4 + 4]);
                af[mi][3] = __float_as_uint(ap[(g + 8) * 20 + t4 + 4]);
            }
            #pragma unroll
            for (int ni = 0; ni < 8; ni++) {
                uint32_t b0 = __float_as_uint(Bb[(kb + t4) * 136 + wn + ni * 8 + g]);
                uint32_t b1 = __float_as_uint(Bb[(kb + t4 + 4) * 136 + wn + ni * 8 + g]);
                mma8(acc[0][ni], af[0], b0, b1);
                mma8(acc[1][ni], af[1], b0, b1);
            }
        }
        // no bottom sync: next iteration's top barrier orders reuse of this stage
    }

    if (PROJ) {
        #pragma unroll
        for (int mi = 0; mi < 2; mi++)
            #pragma unroll
            for (int ni = 0; ni < 8; ni++)
                #pragma unroll
                for (int p = 0; p < 4; p++)
                    acc[mi][ni][p] = tf32r(acc[mi][ni][p]);
    }

    #pragma unroll
    for (int mi = 0; mi < 2; mi++) {
        #pragma unroll
        for (int ni = 0; ni < 8; ni++) {
            int col = bx * 128 + wn + ni * 8 + 2 * t4;
            float2 o0 = make_float2(acc[mi][ni][0], acc[mi][ni][1]);
            float2 o1 = make_float2(acc[mi][ni][2], acc[mi][ni][3]);
            if (!PROJ) {
                float2 bb = *(const float2*)(bias + col);
                o0.x += bb.x; o0.y += bb.y; o1.x += bb.x; o1.y += bb.y;
            }
            int r0 = grow + wm + mi * 16 + g;
            *(float2*)(C + (size_t)r0 * 512 + col) = o0;
            *(float2*)(C + (size_t)(r0 + 8) * 512 + col) = o1;
        }
    }

    if (PROJ && (grow >> 14) < 2) {
        int t = grow >> 14;
        int h = bx * 2 + (wid & 1);
        #pragma unroll
        for (int mi = 0; mi < 2; mi++) {
            #pragma unroll
            for (int half = 0; half < 2; half++) {
                float s = 0.f;
                #pragma unroll
                for (int ni = 0; ni < 8; ni++) {
                    float x = acc[mi][ni][2 * half], y = acc[mi][ni][2 * half + 1];
                    s += x * x + y * y;
                }
                s += __shfl_xor_sync(0xffffffffu, s, 1);
                s += __shfl_xor_sync(0xffffffffu, s, 2);
                if (t4 == 0) {
                    int gr = grow + wm + mi * 16 + g + 8 * half;
                    int r = gr & 16383, bb = r >> 8, n = r & 255;
                    g_norms[t * 131072 + (h * 64 + bb) * 256 + n] = sqrtf(s);
                }
            }
        }
    }
}

// ---------------- 3) chunk stats: raw Gram (tf32 mma) + rank-1 correction ----------------
__global__ __launch_bounds__(256) void stats_kernel()
{
    extern __shared__ float sE[];        // [256][72]
    __shared__ float red[256];
    __shared__ float smu[64];
    __shared__ float r3[3][8];

    int tid = threadIdx.x;
    int bx = blockIdx.x;
    int t = bx >> 9;
    int rest = bx & 511;
    int c = rest >> 3, s = rest & 7;
    int h = c >> 3, b = ((c & 7) << 3) + s;
    const float* base = g_f + (size_t)t * FS + (size_t)(b * 256) * 512 + h * 64;

    for (int idx = tid; idx < 4096; idx += 256) {
        int n = idx >> 4, c4 = (idx & 15) * 4;
        *(float4*)&sE[n * 72 + c4] = *(const float4*)(base + (size_t)n * 512 + c4);
    }
    __syncthreads();

    {
        int i = tid & 63, grp = tid >> 6;
        float sm = 0.f;
        #pragma unroll 8
        for (int n = grp; n < 256; n += 4) sm += sE[n * 72 + i];
        red[tid] = sm;
        __syncthreads();
        if (tid < 64)
            smu[tid] = (red[tid] + red[tid + 64] + red[tid + 128] + red[tid + 192]) * (1.f / 256.f);
        __syncthreads();
    }

    int lane = tid & 31, wid = tid >> 5;
    int g = lane >> 2, t4 = lane & 3;
    int wm = (wid & 3) * 16, wn = (wid >> 2) * 32;
    float gacc[4][4] = {};
    #pragma unroll 4
    for (int ks = 0; ks < 32; ks++) {
        int kb8 = ks * 8;
        uint32_t af[4];
        af[0] = __float_as_uint(sE[(kb8 + t4) * 72 + wm + g]);
        af[1] = __float_as_uint(sE[(kb8 + t4) * 72 + wm + g + 8]);
        af[2] = __float_as_uint(sE[(kb8 + t4 + 4) * 72 + wm + g]);
        af[3] = __float_as_uint(sE[(kb8 + t4 + 4) * 72 + wm + g + 8]);
        #pragma unroll
        for (int ni = 0; ni < 4; ni++) {
            uint32_t b0 = __float_as_uint(sE[(kb8 + t4) * 72 + wn + ni * 8 + g]);
            uint32_t b1 = __float_as_uint(sE[(kb8 + t4 + 4) * 72 + wn + ni * 8 + g]);
            mma8(gacc[ni], af, b0, b1);
        }
    }

    int row0 = wm + g, row1 = wm + g + 8;
    float mr0 = smu[row0] * 256.f, mr1 = smu[row1] * 256.f;
    float tot = 0.f, dsum = 0.f, vsum = 0.f;
    #pragma unroll
    for (int ni = 0; ni < 4; ni++) {
        int c0 = wn + ni * 8 + 2 * t4, c1 = c0 + 1;
        float mc0 = smu[c0], mc1 = smu[c1];
        float g00 = gacc[ni][0] - mr0 * mc0;
        float g01 = gacc[ni][1] - mr0 * mc1;
        float g10 = gacc[ni][2] - mr1 * mc0;
        float g11 = gacc[ni][3] - mr1 * mc1;
        tot += g00 * g00 + g01 * g01 + g10 * g10 + g11 * g11;
        if (row0 == c0) { dsum += g00 * g00; vsum += fmaxf(0.f, 1.f - sqrtf(g00 * (1.f / 255.f) + 1e-8f)); }
        if (row0 == c1) { dsum += g01 * g01; vsum += fmaxf(0.f, 1.f - sqrtf(g01 * (1.f / 255.f) + 1e-8f)); }
        if (row1 == c0) { dsum += g10 * g10; vsum += fmaxf(0.f, 1.f - sqrtf(g10 * (1.f / 255.f) + 1e-8f)); }
        if (row1 == c1) { dsum += g11 * g11; vsum += fmaxf(0.f, 1.f - sqrtf(g11 * (1.f / 255.f) + 1e-8f)); }
    }

    float a0 = warp_sum(tot), a1 = warp_sum(dsum), a2 = warp_sum(vsum);
    if (!lane) { r3[0][wid] = a0; r3[1][wid] = a1; r3[2][wid] = a2; }
    __syncthreads();
    if (tid == 0) {
        float T = 0.f, D = 0.f, V = 0.f;
        #pragma unroll
        for (int i = 0; i < 8; i++) { T += r3[0][i]; D += r3[1][i]; V += r3[2][i]; }
        g_part[bx * 2 + 0] = V * (1.f / 512.f);
        g_part[bx * 2 + 1] = (T - D) * (1.f / (255.f * 255.f * 64.f * 8.f));
    }
}

// ---------------- 4) fused attention (unified grid) ----------------
__global__ __launch_bounds__(256) void attn_kernel(
    const float* __restrict__ cl, const float* __restrict__ vl)
{
    extern __shared__ float sh[];
    float* Qs  = sh;                       // [128][68]
    float* Ks  = sh + 128 * 68;            // [64][68]
    float* Vs  = sh + 128 * 68 + 64 * 68;  // [64][72]
    float* Ssm = Vs + 64 * 72;             // [128][68]

    int tid = threadIdx.x, lane = tid & 31, wid = tid >> 5;
    int g = lane >> 2, t4 = lane & 3;
    int wm = (wid >> 1) * 32, wn = (wid & 1) * 32;
    int nt = blockIdx.x, hb = blockIdx.y;
    int h = hb >> 6, b = hb & 63, c = hb >> 3;

    const float* qb = g_f + (size_t)(b * 256 + nt * 128) * 512 + h * 64;
    const float* kb = g_f + FS + (size_t)(b * 256) * 512 + h * 64;
    const float* vb = g_f + 2 * FS + (size_t)(b * 256) * 512 + h * 64;

    {
        int lrow = tid >> 4, lc4 = (tid & 15) * 4;
        #pragma unroll
        for (int l = 0; l < 8; l++) {
            int row = l * 16 + lrow;
            *(float4*)&Qs[row * 68 + lc4] = *(const float4*)(qb + (size_t)row * 512 + lc4);
        }
    }

    float cw = 1.f / (1.f + expf(-cl[0]));
    float vw = 1.f / (1.f + expf(-vl[0]));
    float cosw = 1.f - cw - vw;
    float Vq = 0.f, Cq = 0.f, Vk = 0.f, Ck = 0.f;
    #pragma unroll
    for (int s = 0; s < 8; s++) {
        Vq += g_part[(c * 8 + s) * 2];
        Cq += g_part[(c * 8 + s) * 2 + 1];
        Vk += g_part[(512 + c * 8 + s) * 2];
        Ck += g_part[(512 + c * 8 + s) * 2 + 1];
    }
    float biasv = cw * (Cq * Ck) + vw * (Vq * Vk);

    float qinv[2][2];
    #pragma unroll
    for (int mi = 0; mi < 2; mi++)
        #pragma unroll
        for (int half = 0; half < 2; half++) {
            int n = nt * 128 + wm + mi * 16 + g + 8 * half;
            qinv[mi][half] = cosw / g_norms[hb * 256 + n];
        }

    int krow = tid >> 2;
    int kc0 = (tid & 3) * 4;

    float oacc[2][4][4] = {};
    for (int mc = 0; mc < 4; mc++) {
        #pragma unroll
        for (int l = 0; l < 4; l++) {
            int col = kc0 + l * 16;
            *(float4*)&Ks[krow * 68 + col] =
                *(const float4*)(kb + (size_t)(mc * 64 + krow) * 512 + col);
            *(float4*)&Vs[krow * 72 + col] =
                *(const float4*)(vb + (size_t)(mc * 64 + krow) * 512 + col);
        }
        __syncthreads();

        float sacc[2][4][4] = {};
        #pragma unroll
        for (int ks = 0; ks < 8; ks++) {
            int kb8 = ks * 8;
            uint32_t af[2][4];
            #pragma unroll
            for (int mi = 0; mi < 2; mi++) {
                const float* ap = &Qs[(wm + mi * 16) * 68 + kb8];
                af[mi][0] = __float_as_uint(ap[g * 68 + t4]);
                af[mi][1] = __float_as_uint(ap[(g + 8) * 68 + t4]);
                af[mi][2] = __float_as_uint(ap[g * 68 + t4 + 4]);
                af[mi][3] = __float_as_uint(ap[(g + 8) * 68 + t4 + 4]);
            }
            #pragma unroll
            for (int ni = 0; ni < 4; ni++) {
                uint32_t b0 = __float_as_uint(Ks[(wn + ni * 8 + g) * 68 + kb8 + t4]);
                uint32_t b1 = __float_as_uint(Ks[(wn + ni * 8 + g) * 68 + kb8 + t4 + 4]);
                mma8(sacc[0][ni], af[0], b0, b1);
                mma8(sacc[1][ni], af[1], b0, b1);
            }
        }

        #pragma unroll
        for (int ni = 0; ni < 4; ni++) {
            int ml = wn + ni * 8 + 2 * t4;
            int m0 = mc * 64 + ml;
            float ki0 = 1.f / g_norms[131072 + hb * 256 + m0];
            float ki1 = 1.f / g_norms[131072 + hb * 256 + m0 + 1];
            #pragma unroll
            for (int mi = 0; mi < 2; mi++) {
                #pragma unroll
                for (int half = 0; half < 2; half++) {
                    int nl = wm + mi * 16 + g + 8 * half;
                    float2 o = make_float2(
                        tf32r(qinv[mi][half] * sacc[mi][ni][2 * half] * ki0 + biasv),
                        tf32r(qinv[mi][half] * sacc[mi][ni][2 * half + 1] * ki1 + biasv));
                    *(float2*)&Ssm[nl * 68 + ml] = o;
                }
            }
        }
        __syncthreads();

        #pragma unroll
        for (int ks = 0; ks < 8; ks++) {
            int kb8 = ks * 8;
            uint32_t af[2][4];
            #pragma unroll
            for (int mi = 0; mi < 2; mi++) {
                const float* ap = &Ssm[(wm + mi * 16) * 68 + kb8];
                af[mi][0] = __float_as_uint(ap[g * 68 + t4]);
                af[mi][1] = __float_as_uint(ap[(g + 8) * 68 + t4]);
                af[mi][2] = __float_as_uint(ap[g * 68 + t4 + 4]);
                af[mi][3] = __float_as_uint(ap[(g + 8) * 68 + t4 + 4]);
            }
            #pragma unroll
            for (int ni = 0; ni < 4; ni++) {
                uint32_t b0 = __float_as_uint(Vs[(kb8 + t4) * 72 + wn + ni * 8 + g]);
                uint32_t b1 = __float_as_uint(Vs[(kb8 + t4 + 4) * 72 + wn + ni * 8 + g]);
                mma8(oacc[0][ni], af[0], b0, b1);
                mma8(oacc[1][ni], af[1], b0, b1);
            }
        }
        __syncthreads();
    }

    #pragma unroll
    for (int mi = 0; mi < 2; mi++) {
        #pragma unroll
        for (int ni = 0; ni < 4; ni++) {
            int col = wn + ni * 8 + 2 * t4;
            int n0 = nt * 128 + wm + mi * 16 + g;
            *(float2*)(g_att + (size_t)(b * 256 + n0) * 512 + h * 64 + col) =
                make_float2(tf32r(oacc[mi][ni][0]), tf32r(oacc[mi][ni][1]));
            *(float2*)(g_att + (size_t)(b * 256 + n0 + 8) * 512 + h * 64 + col) =
                make_float2(tf32r(oacc[mi][ni][2]), tf32r(oacc[mi][ni][3]));
        }
    }
}

// ---------------- launch ----------------
extern "C" void kernel_launch(void* const* d_in, const int* in_sizes, int n_in,
                              void* d_out, int out_size)
{
    const float* q   = (const float*)d_in[0];
    const float* k   = (const float*)d_in[1];
    const float* v   = (const float*)d_in[2];
    const float* gma = (const float*)d_in[3];
    const float* bta = (const float*)d_in[4];
    const float* Win = (const float*)d_in[5];
    const float* Wout= (const float*)d_in[6];
    const float* bout= (const float*)d_in[7];
    const float* covl= (const float*)d_in[8];
    const float* varl= (const float*)d_in[9];
    float* out = (float*)d_out;

    void *pxn, *pf, *patt, *pwin, *pwout;
    cudaGetSymbolAddress(&pxn, g_xn);
    cudaGetSymbolAddress(&pf, g_f);
    cudaGetSymbolAddress(&patt, g_att);
    cudaGetSymbolAddress(&pwin, g_win);
    cudaGetSymbolAddress(&pwout, g_wout);

    constexpr int ATTN_SMEM  = (128 * 68 + 64 * 68 + 64 * 72 + 128 * 68) * 4;
    constexpr int STATS_SMEM = 256 * 72 * 4;

    static cudaStream_t s2;
    static cudaEvent_t evRoot, evW, evV, evQK, evS;
    static bool init_done = false;
    if (!init_done) {
        cudaFuncSetAttribute(attn_kernel,  cudaFuncAttributeMaxDynamicSharedMemorySize, ATTN_SMEM);
        cudaFuncSetAttribute(stats_kernel, cudaFuncAttributeMaxDynamicSharedMemorySize, STATS_SMEM);
        cudaStreamCreateWithFlags(&s2, cudaStreamNonBlocking);
        cudaEventCreateWithFlags(&evRoot, cudaEventDisableTiming);
        cudaEventCreateWithFlags(&evW, cudaEventDisableTiming);
        cudaEventCreateWithFlags(&evV, cudaEventDisableTiming);
        cudaEventCreateWithFlags(&evQK, cudaEventDisableTiming);
        cudaEventCreateWithFlags(&evS, cudaEventDisableTiming);
        init_done = true;
    }

    // fork s2 from the capturing stream
    cudaEventRecord(evRoot, 0);
    cudaStreamWaitEvent(s2, evRoot, 0);

    // s2: wround, then ln for v rows
    wround_kernel<<<256, 256, 0, s2>>>(Win, Wout);
    cudaEventRecord(evW, s2);
    ln_kernel<<<2048, 256, 0, s2>>>(q, k, v, gma, bta, 4096);   // v rows
    cudaEventRecord(evV, s2);

    // main: ln for q,k rows
    ln_kernel<<<4096, 256>>>(q, k, v, gma, bta, 0);
    cudaStreamWaitEvent(0, evW, 0);

    // proj q,k rows
    mm_kernel<true><<<dim3(4, 256), 256>>>((const float*)pxn, (const float*)pwin,
                                           (float*)pf, nullptr, 0);
    cudaEventRecord(evQK, 0);

    // stats on s2, concurrent with proj_v
    cudaStreamWaitEvent(s2, evQK, 0);
    stats_kernel<<<1024, 256, STATS_SMEM, s2>>>();
    cudaEventRecord(evS, s2);

    // proj v rows on main (needs ln_v done)
    cudaStreamWaitEvent(0, evV, 0);
    mm_kernel<true><<<dim3(4, 128), 256>>>((const float*)pxn, (const float*)pwin,
                                           (float*)pf, nullptr, 256);

    // join stats, then unified attention
    cudaStreamWaitEvent(0, evS, 0);
    attn_kernel<<<dim3(2, 512), 256, ATTN_SMEM>>>(covl, varl);

    // output GEMM
    mm_kernel<false><<<dim3(4, 128), 256>>>((const float*)patt, (const float*)pwout,
                                            out, bout, 0);
}

// round 17
// speedup vs baseline: 1.1832x; 1.0113x over previous
#include <cuda_runtime.h>
#include <math.h>
#include <stdint.h>

constexpr size_t FS = (size_t)16384 * 512;

__device__ float g_xn[3 * FS];                      // LN output (tf32-rounded)
__device__ float g_f[3 * FS];                       // projected features (tf32-rounded)
__device__ float g_att[FS];                         // attention out (tf32-rounded)
__device__ float g_win[512 * 512];
__device__ float g_wout[512 * 512];
__device__ float g_rnorms[2 * 512 * 256];           // 1/qn, 1/kn  [t][hb][n]
__device__ float g_part[2048];                      // stats partials [t][c][s][2]

__device__ __forceinline__ float warp_sum(float v) {
    #pragma unroll
    for (int o = 16; o; o >>= 1) v += __shfl_xor_sync(0xffffffffu, v, o);
    return v;
}
__device__ __forceinline__ float tf32r(float x) {
    uint32_t u;
    asm("cvt.rna.tf32.f32 %0, %1;" : "=r"(u) : "f"(x));
    return __uint_as_float(u);
}
__device__ __forceinline__ void mma8(float c[4], const uint32_t a[4], uint32_t b0, uint32_t b1) {
    asm volatile(
        "mma.sync.aligned.m16n8k8.row.col.f32.tf32.tf32.f32 "
        "{%0,%1,%2,%3},{%4,%5,%6,%7},{%8,%9},{%0,%1,%2,%3};"
        : "+f"(c[0]), "+f"(c[1]), "+f"(c[2]), "+f"(c[3])
        : "r"(a[0]), "r"(a[1]), "r"(a[2]), "r"(a[3]), "r"(b0), "r"(b1));
}
__device__ __forceinline__ void cp16(uint32_t saddr, const void* gptr) {
    asm volatile("cp.async.cg.shared.global [%0], [%1], 16;" :: "r"(saddr), "l"(gptr));
}
__device__ __forceinline__ void cp_commit() { asm volatile("cp.async.commit_group;"); }
__device__ __forceinline__ void cp_wait1()  { asm volatile("cp.async.wait_group 1;"); }
__device__ __forceinline__ void cp_wait0()  { asm volatile("cp.async.wait_group 0;"); }

// ---------------- 0) round weights once ----------------
__global__ __launch_bounds__(256) void wround_kernel(
    const float* __restrict__ Win, const float* __restrict__ Wout)
{
    int idx = (blockIdx.x * 256 + threadIdx.x) * 4;
    float4 a = *(const float4*)(Win + idx);
    a.x = tf32r(a.x); a.y = tf32r(a.y); a.z = tf32r(a.z); a.w = tf32r(a.w);
    *(float4*)(g_win + idx) = a;
    float4 b = *(const float4*)(Wout + idx);
    b.x = tf32r(b.x); b.y = tf32r(b.y); b.z = tf32r(b.z); b.w = tf32r(b.w);
    *(float4*)(g_wout + idx) = b;
}

// ---------------- 1) LayerNorm, writes tf32-rounded output (+ block offset) ----------------
__global__ __launch_bounds__(256) void ln_kernel(
    const float* __restrict__ q, const float* __restrict__ k, const float* __restrict__ v,
    const float* __restrict__ gma, const float* __restrict__ bta, int blockoff)
{
    int warp = threadIdx.x >> 5, lane = threadIdx.x & 31;
    int row = (blockIdx.x + blockoff) * 8 + warp;
    int t = row >> 14, r = row & 16383;
    const float* src = (t == 0 ? q : (t == 1 ? k : v)) + (size_t)r * 512;
    float x[16], s = 0.f;
    #pragma unroll
    for (int i = 0; i < 16; i++) { x[i] = src[lane + 32 * i]; s += x[i]; }
    s = warp_sum(s);
    float mu = s * (1.f / 512.f), ss = 0.f;
    #pragma unroll
    for (int i = 0; i < 16; i++) { float d = x[i] - mu; ss += d * d; }
    ss = warp_sum(ss);
    float rs = rsqrtf(ss * (1.f / 512.f) + 1e-5f);
    float* dst = g_xn + (size_t)row * 512;
    #pragma unroll
    for (int i = 0; i < 16; i++) {
        int c = lane + 32 * i;
        dst[c] = tf32r((x[i] - mu) * rs * gma[c] + bta[c]);
    }
}

// ---- 2/6) tf32 GEMM 128x128, 8 warps of 32x64, cp.async 3-stage, 1 sync/iter ----
template<bool PROJ>
__global__ __launch_bounds__(256, 2) void mm_kernel(
    const float* __restrict__ A, const float* __restrict__ B,
    float* __restrict__ C, const float* __restrict__ bias, int rowoff)
{
    __shared__ float As[3][128 * 20];
    __shared__ float Bs[3][16 * 136];

    int tid = threadIdx.x, lane = tid & 31, wid = tid >> 5;
    int g = lane >> 2, t4 = lane & 3;
    int wm = (wid >> 1) * 32, wn = (wid & 1) * 64;
    int bx = blockIdx.x;
    int grow = (blockIdx.y + rowoff) * 128;

    int arow = tid >> 2, ac4 = (tid & 3) * 4;
    const float* srcA[2];
    #pragma unroll
    for (int l = 0; l < 2; l++)
        srcA[l] = A + (size_t)(grow + l * 64 + arow) * 512;
    int brow = tid >> 5, bcol = (tid & 31) * 4;
    const float* Bbase = B + (size_t)bx * 128 + bcol;

    uint32_t sAbase = (uint32_t)__cvta_generic_to_shared(&As[0][0]);
    uint32_t sBbase = (uint32_t)__cvta_generic_to_shared(&Bs[0][0]);
    constexpr uint32_t ASTG = 128 * 20 * 4;
    constexpr uint32_t BSTG = 16 * 136 * 4;

    float acc[2][8][4] = {};

    #pragma unroll
    for (int st = 0; st < 2; st++) {
        int bk = st * 16;
        #pragma unroll
        for (int l = 0; l < 2; l++) {
            cp16(sAbase + st * ASTG + ((l * 64 + arow) * 20 + ac4) * 4, srcA[l] + bk + ac4);
            cp16(sBbase + st * BSTG + ((l * 8 + brow) * 136 + bcol) * 4,
                 Bbase + (size_t)(bk + l * 8 + brow) * 512);
        }
        cp_commit();
    }

    for (int t = 0; t < 32; t++) {
        if (t == 31) cp_wait0(); else cp_wait1();
        __syncthreads();

        if (t + 2 < 32) {
            int st = (t + 2) % 3;
            int bk = (t + 2) * 16;
            #pragma unroll
            for (int l = 0; l < 2; l++) {
                cp16(sAbase + st * ASTG + ((l * 64 + arow) * 20 + ac4) * 4, srcA[l] + bk + ac4);
                cp16(sBbase + st * BSTG + ((l * 8 + brow) * 136 + bcol) * 4,
                     Bbase + (size_t)(bk + l * 8 + brow) * 512);
            }
            cp_commit();
        }

        const float* Ab = As[t % 3];
        const float* Bb = Bs[t % 3];
        #pragma unroll
        for (int ks = 0; ks < 2; ks++) {
            int kb = ks * 8;
            uint32_t af[2][4];
            #pragma unroll
            for (int mi = 0; mi < 2; mi++) {
                const float* ap = &Ab[(wm + mi * 16) * 20 + kb];
                af[mi][0] = __float_as_uint(ap[g * 20 + t4]);
                af[mi][1] = __float_as_uint(ap[(g + 8) * 20 + t4]);
                af[mi][2] = __float_as_uint(ap[g * 20 + t4 + 4]);
                af[mi][3] = __float_as_uint(ap[(g + 8) * 20 + t4 + 4]);
            }
            #pragma unroll
            for (int ni = 0; ni < 8; ni++) {
                uint32_t b0 = __float_as_uint(Bb[(kb + t4) * 136 + wn + ni * 8 + g]);
                uint32_t b1 = __float_as_uint(Bb[(kb + t4 + 4) * 136 + wn + ni * 8 + g]);
                mma8(acc[0][ni], af[0], b0, b1);
                mma8(acc[1][ni], af[1], b0, b1);
            }
        }
    }

    if (PROJ) {
        #pragma unroll
        for (int mi = 0; mi < 2; mi++)
            #pragma unroll
            for (int ni = 0; ni < 8; ni++)
                #pragma unroll
                for (int p = 0; p < 4; p++)
                    acc[mi][ni][p] = tf32r(acc[mi][ni][p]);
    }

    #pragma unroll
    for (int mi = 0; mi < 2; mi++) {
        #pragma unroll
        for (int ni = 0; ni < 8; ni++) {
            int col = bx * 128 + wn + ni * 8 + 2 * t4;
            float2 o0 = make_float2(acc[mi][ni][0], acc[mi][ni][1]);
            float2 o1 = make_float2(acc[mi][ni][2], acc[mi][ni][3]);
            if (!PROJ) {
                float2 bb = *(const float2*)(bias + col);
                o0.x += bb.x; o0.y += bb.y; o1.x += bb.x; o1.y += bb.y;
            }
            int r0 = grow + wm + mi * 16 + g;
            *(float2*)(C + (size_t)r0 * 512 + col) = o0;
            *(float2*)(C + (size_t)(r0 + 8) * 512 + col) = o1;
        }
    }

    if (PROJ && (grow >> 14) < 2) {
        int t = grow >> 14;
        int h = bx * 2 + (wid & 1);
        #pragma unroll
        for (int mi = 0; mi < 2; mi++) {
            #pragma unroll
            for (int half = 0; half < 2; half++) {
                float s = 0.f;
                #pragma unroll
                for (int ni = 0; ni < 8; ni++) {
                    float x = acc[mi][ni][2 * half], y = acc[mi][ni][2 * half + 1];
                    s += x * x + y * y;
                }
                s += __shfl_xor_sync(0xffffffffu, s, 1);
                s += __shfl_xor_sync(0xffffffffu, s, 2);
                if (t4 == 0) {
                    int gr = grow + wm + mi * 16 + g + 8 * half;
                    int r = gr & 16383, bb = r >> 8, n = r & 255;
                    g_rnorms[t * 131072 + (h * 64 + bb) * 256 + n] = rsqrtf(s);
                }
            }
        }
    }
}

// ---------------- 3) chunk stats: raw Gram (tf32 mma) + rank-1 correction ----------------
__global__ __launch_bounds__(256) void stats_kernel()
{
    extern __shared__ float sE[];        // [256][72]
    __shared__ float red[256];
    __shared__ float smu[64];
    __shared__ float r3[3][8];

    int tid = threadIdx.x;
    int bx = blockIdx.x;
    int t = bx >> 9;
    int rest = bx & 511;
    int c = rest >> 3, s = rest & 7;
    int h = c >> 3, b = ((c & 7) << 3) + s;
    const float* base = g_f + (size_t)t * FS + (size_t)(b * 256) * 512 + h * 64;

    for (int idx = tid; idx < 4096; idx += 256) {
        int n = idx >> 4, c4 = (idx & 15) * 4;
        *(float4*)&sE[n * 72 + c4] = *(const float4*)(base + (size_t)n * 512 + c4);
    }
    __syncthreads();

    {
        int i = tid & 63, grp = tid >> 6;
        float sm = 0.f;
        #pragma unroll 8
        for (int n = grp; n < 256; n += 4) sm += sE[n * 72 + i];
        red[tid] = sm;
        __syncthreads();
        if (tid < 64)
            smu[tid] = (red[tid] + red[tid + 64] + red[tid + 128] + red[tid + 192]) * (1.f / 256.f);
        __syncthreads();
    }

    int lane = tid & 31, wid = tid >> 5;
    int g = lane >> 2, t4 = lane & 3;
    int wm = (wid & 3) * 16, wn = (wid >> 2) * 32;
    float gacc[4][4] = {};
    #pragma unroll 4
    for (int ks = 0; ks < 32; ks++) {
        int kb8 = ks * 8;
        uint32_t af[4];
        af[0] = __float_as_uint(sE[(kb8 + t4) * 72 + wm + g]);
        af[1] = __float_as_uint(sE[(kb8 + t4) * 72 + wm + g + 8]);
        af[2] = __float_as_uint(sE[(kb8 + t4 + 4) * 72 + wm + g]);
        af[3] = __float_as_uint(sE[(kb8 + t4 + 4) * 72 + wm + g + 8]);
        #pragma unroll
        for (int ni = 0; ni < 4; ni++) {
            uint32_t b0 = __float_as_uint(sE[(kb8 + t4) * 72 + wn + ni * 8 + g]);
            uint32_t b1 = __float_as_uint(sE[(kb8 + t4 + 4) * 72 + wn + ni * 8 + g]);
            mma8(gacc[ni], af, b0, b1);
        }
    }

    int row0 = wm + g, row1 = wm + g + 8;
    float mr0 = smu[row0] * 256.f, mr1 = smu[row1] * 256.f;
    float tot = 0.f, dsum = 0.f, vsum = 0.f;
    #pragma unroll
    for (int ni = 0; ni < 4; ni++) {
        int c0 = wn + ni * 8 + 2 * t4, c1 = c0 + 1;
        float mc0 = smu[c0], mc1 = smu[c1];
        float g00 = gacc[ni][0] - mr0 * mc0;
        float g01 = gacc[ni][1] - mr0 * mc1;
        float g10 = gacc[ni][2] - mr1 * mc0;
        float g11 = gacc[ni][3] - mr1 * mc1;
        tot += g00 * g00 + g01 * g01 + g10 * g10 + g11 * g11;
        if (row0 == c0) { dsum += g00 * g00; vsum += fmaxf(0.f, 1.f - sqrtf(g00 * (1.f / 255.f) + 1e-8f)); }
        if (row0 == c1) { dsum += g01 * g01; vsum += fmaxf(0.f, 1.f - sqrtf(g01 * (1.f / 255.f) + 1e-8f)); }
        if (row1 == c0) { dsum += g10 * g10; vsum += fmaxf(0.f, 1.f - sqrtf(g10 * (1.f / 255.f) + 1e-8f)); }
        if (row1 == c1) { dsum += g11 * g11; vsum += fmaxf(0.f, 1.f - sqrtf(g11 * (1.f / 255.f) + 1e-8f)); }
    }

    float a0 = warp_sum(tot), a1 = warp_sum(dsum), a2 = warp_sum(vsum);
    if (!lane) { r3[0][wid] = a0; r3[1][wid] = a1; r3[2][wid] = a2; }
    __syncthreads();
    if (tid == 0) {
        float T = 0.f, D = 0.f, V = 0.f;
        #pragma unroll
        for (int i = 0; i < 8; i++) { T += r3[0][i]; D += r3[1][i]; V += r3[2][i]; }
        g_part[bx * 2 + 0] = V * (1.f / 512.f);
        g_part[bx * 2 + 1] = (T - D) * (1.f / (255.f * 255.f * 64.f * 8.f));
    }
}

// ---------------- 4) fused attention (reciprocal norms: no divisions) ----------------
__global__ __launch_bounds__(256) void attn_kernel(
    const float* __restrict__ cl, const float* __restrict__ vl)
{
    extern __shared__ float sh[];
    float* Qs  = sh;                       // [128][68]
    float* Ks  = sh + 128 * 68;            // [64][68]
    float* Vs  = sh + 128 * 68 + 64 * 68;  // [64][72]
    float* Ssm = Vs + 64 * 72;             // [128][68]

    int tid = threadIdx.x, lane = tid & 31, wid = tid >> 5;
    int g = lane >> 2, t4 = lane & 3;
    int wm = (wid >> 1) * 32, wn = (wid & 1) * 32;
    int nt = blockIdx.x, hb = blockIdx.y;
    int h = hb >> 6, b = hb & 63, c = hb >> 3;

    const float* qb = g_f + (size_t)(b * 256 + nt * 128) * 512 + h * 64;
    const float* kb = g_f + FS + (size_t)(b * 256) * 512 + h * 64;
    const float* vb = g_f + 2 * FS + (size_t)(b * 256) * 512 + h * 64;

    {
        int lrow = tid >> 4, lc4 = (tid & 15) * 4;
        #pragma unroll
        for (int l = 0; l < 8; l++) {
            int row = l * 16 + lrow;
            *(float4*)&Qs[row * 68 + lc4] = *(const float4*)(qb + (size_t)row * 512 + lc4);
        }
    }

    float cw = 1.f / (1.f + expf(-cl[0]));
    float vw = 1.f / (1.f + expf(-vl[0]));
    float cosw = 1.f - cw - vw;
    float Vq = 0.f, Cq = 0.f, Vk = 0.f, Ck = 0.f;
    #pragma unroll
    for (int s = 0; s < 8; s++) {
        Vq += g_part[(c * 8 + s) * 2];
        Cq += g_part[(c * 8 + s) * 2 + 1];
        Vk += g_part[(512 + c * 8 + s) * 2];
        Ck += g_part[(512 + c * 8 + s) * 2 + 1];
    }
    float biasv = cw * (Cq * Ck) + vw * (Vq * Vk);

    float qinv[2][2];
    #pragma unroll
    for (int mi = 0; mi < 2; mi++)
        #pragma unroll
        for (int half = 0; half < 2; half++) {
            int n = nt * 128 + wm + mi * 16 + g + 8 * half;
            qinv[mi][half] = cosw * g_rnorms[hb * 256 + n];
        }

    int krow = tid >> 2;
    int kc0 = (tid & 3) * 4;

    float oacc[2][4][4] = {};
    for (int mc = 0; mc < 4; mc++) {
        #pragma unroll
        for (int l = 0; l < 4; l++) {
            int col = kc0 + l * 16;
            *(float4*)&Ks[krow * 68 + col] =
                *(const float4*)(kb + (size_t)(mc * 64 + krow) * 512 + col);
            *(float4*)&Vs[krow * 72 + col] =
                *(const float4*)(vb + (size_t)(mc * 64 + krow) * 512 + col);
        }
        __syncthreads();

        float sacc[2][4][4] = {};
        #pragma unroll
        for (int ks = 0; ks < 8; ks++) {
            int kb8 = ks * 8;
            uint32_t af[2][4];
            #pragma unroll
            for (int mi = 0; mi < 2; mi++) {
                const float* ap = &Qs[(wm + mi * 16) * 68 + kb8];
                af[mi][0] = __float_as_uint(ap[g * 68 + t4]);
                af[mi][1] = __float_as_uint(ap[(g + 8) * 68 + t4]);
                af[mi][2] = __float_as_uint(ap[g * 68 + t4 + 4]);
                af[mi][3] = __float_as_uint(ap[(g + 8) * 68 + t4 + 4]);
            }
            #pragma unroll
            for (int ni = 0; ni < 4; ni++) {
                uint32_t b0 = __float_as_uint(Ks[(wn + ni * 8 + g) * 68 + kb8 + t4]);
                uint32_t b1 = __float_as_uint(Ks[(wn + ni * 8 + g) * 68 + kb8 + t4 + 4]);
                mma8(sacc[0][ni], af[0], b0, b1);
                mma8(sacc[1][ni], af[1], b0, b1);
            }
        }

        #pragma unroll
        for (int ni = 0; ni < 4; ni++) {
            int ml = wn + ni * 8 + 2 * t4;
            int m0 = mc * 64 + ml;
            float ki0 = g_rnorms[131072 + hb * 256 + m0];
            float ki1 = g_rnorms[131072 + hb * 256 + m0 + 1];
            #pragma unroll
            for (int mi = 0; mi < 2; mi++) {
                #pragma unroll
                for (int half = 0; half < 2; half++) {
                    int nl = wm + mi * 16 + g + 8 * half;
                    float2 o = make_float2(
                        tf32r(qinv[mi][half] * sacc[mi][ni][2 * half] * ki0 + biasv),
                        tf32r(qinv[mi][half] * sacc[mi][ni][2 * half + 1] * ki1 + biasv));
                    *(float2*)&Ssm[nl * 68 + ml] = o;
                }
            }
        }
        __syncthreads();

        #pragma unroll
        for (int ks = 0; ks < 8; ks++) {
            int kb8 = ks * 8;
            uint32_t af[2][4];
            #pragma unroll
            for (int mi = 0; mi < 2; mi++) {
                const float* ap = &Ssm[(wm + mi * 16) * 68 + kb8];
                af[mi][0] = __float_as_uint(ap[g * 68 + t4]);
                af[mi][1] = __float_as_uint(ap[(g + 8) * 68 + t4]);
                af[mi][2] = __float_as_uint(ap[g * 68 + t4 + 4]);
                af[mi][3] = __float_as_uint(ap[(g + 8) * 68 + t4 + 4]);
            }
            #pragma unroll
            for (int ni = 0; ni < 4; ni++) {
                uint32_t b0 = __float_as_uint(Vs[(kb8 + t4) * 72 + wn + ni * 8 + g]);
                uint32_t b1 = __float_as_uint(Vs[(kb8 + t4 + 4) * 72 + wn + ni * 8 + g]);
                mma8(oacc[0][ni], af[0], b0, b1);
                mma8(oacc[1][ni], af[1], b0, b1);
            }
        }
        __syncthreads();
    }

    #pragma unroll
    for (int mi = 0; mi < 2; mi++) {
        #pragma unroll
        for (int ni = 0; ni < 4; ni++) {
            int col = wn + ni * 8 + 2 * t4;
            int n0 = nt * 128 + wm + mi * 16 + g;
            *(float2*)(g_att + (size_t)(b * 256 + n0) * 512 + h * 64 + col) =
                make_float2(tf32r(oacc[mi][ni][0]), tf32r(oacc[mi][ni][1]));
            *(float2*)(g_att + (size_t)(b * 256 + n0 + 8) * 512 + h * 64 + col) =
                make_float2(tf32r(oacc[mi][ni][2]), tf32r(oacc[mi][ni][3]));
        }
    }
}

// ---------------- launch ----------------
extern "C" void kernel_launch(void* const* d_in, const int* in_sizes, int n_in,
                              void* d_out, int out_size)
{
    const float* q   = (const float*)d_in[0];
    const float* k   = (const float*)d_in[1];
    const float* v   = (const float*)d_in[2];
    const float* gma = (const float*)d_in[3];
    const float* bta = (const float*)d_in[4];
    const float* Win = (const float*)d_in[5];
    const float* Wout= (const float*)d_in[6];
    const float* bout= (const float*)d_in[7];
    const float* covl= (const float*)d_in[8];
    const float* varl= (const float*)d_in[9];
    float* out = (float*)d_out;

    void *pxn, *pf, *patt, *pwin, *pwout;
    cudaGetSymbolAddress(&pxn, g_xn);
    cudaGetSymbolAddress(&pf, g_f);
    cudaGetSymbolAddress(&patt, g_att);
    cudaGetSymbolAddress(&pwin, g_win);
    cudaGetSymbolAddress(&pwout, g_wout);

    constexpr int ATTN_SMEM  = (128 * 68 + 64 * 68 + 64 * 72 + 128 * 68) * 4;
    constexpr int STATS_SMEM = 256 * 72 * 4;

    static cudaStream_t s2;
    static cudaEvent_t evRoot, evW, evV, evQK, evS;
    static bool init_done = false;
    if (!init_done) {
        cudaFuncSetAttribute(attn_kernel,  cudaFuncAttributeMaxDynamicSharedMemorySize, ATTN_SMEM);
        cudaFuncSetAttribute(stats_kernel, cudaFuncAttributeMaxDynamicSharedMemorySize, STATS_SMEM);
        cudaStreamCreateWithFlags(&s2, cudaStreamNonBlocking);
        cudaEventCreateWithFlags(&evRoot, cudaEventDisableTiming);
        cudaEventCreateWithFlags(&evW, cudaEventDisableTiming);
        cudaEventCreateWithFlags(&evV, cudaEventDisableTiming);
        cudaEventCreateWithFlags(&evQK, cudaEventDisableTiming);
        cudaEventCreateWithFlags(&evS, cudaEventDisableTiming);
        init_done = true;
    }

    // fork s2 from the capturing stream
    cudaEventRecord(evRoot, 0);
    cudaStreamWaitEvent(s2, evRoot, 0);

    // s2: wround, then ln for v rows
    wround_kernel<<<256, 256, 0, s2>>>(Win, Wout);
    cudaEventRecord(evW, s2);
    ln_kernel<<<2048, 256, 0, s2>>>(q, k, v, gma, bta, 4096);   // v rows
    cudaEventRecord(evV, s2);

    // main: ln for q,k rows
    ln_kernel<<<4096, 256>>>(q, k, v, gma, bta, 0);
    cudaStreamWaitEvent(0, evW, 0);

    // proj q,k rows
    mm_kernel<true><<<dim3(4, 256), 256>>>((const float*)pxn, (const float*)pwin,
                                           (float*)pf, nullptr, 0);
    cudaEventRecord(evQK, 0);

    // stats on s2, concurrent with proj_v
    cudaStreamWaitEvent(s2, evQK, 0);
    stats_kernel<<<1024, 256, STATS_SMEM, s2>>>();
    cudaEventRecord(evS, s2);

    // proj v rows on main (needs ln_v done)
    cudaStreamWaitEvent(0, evV, 0);
    mm_kernel<true><<<dim3(4, 128), 256>>>((const float*)pxn, (const float*)pwin,
                                           (float*)pf, nullptr, 256);

    // join stats, then unified attention
    cudaStreamWaitEvent(0, evS, 0);
    attn_kernel<<<dim3(2, 512), 256, ATTN_SMEM>>>(covl, varl);

    // output GEMM
    mm_kernel<false><<<dim3(4, 128), 256>>>((const float*)patt, (const float*)pwout,
                                            out, bout, 0);
}